// round 9
// baseline (speedup 1.0000x reference)
#include <cuda_runtime.h>
#include <cuda_bf16.h>
#include <cstdint>
#include <cstring>
#include <math.h>

// ---------------- problem constants ----------------
#define T_STEPS 30
#define ISZ     100
#define HSZ     256
#define NSEQ    5120
#define NBATCH  512

// ---------------- device scratch (allocation-free rule) ----------------
__device__ __nv_bfloat16 g_Ax[T_STEPS][40][2][128][128];   // [t][mt][img][row][k]  x, k pad 100->128
__device__ __nv_bfloat16 g_Ah[2][2][40][2][128][256];      // [par][dir][mt][img][row][k]
__device__ __nv_bfloat16 g_Bx[2][8][2][128][128];          // [dir][nt8][img][c'][k]  Wih, gate-interleaved
__device__ __nv_bfloat16 g_Bh[2][8][2][128][256];          // [dir][nt8][img][c'][k]  Whh
__device__ float g_bias[2][1024];                           // [dir][c'=h*4+g]
__device__ float g_c[2 * NSEQ * HSZ];
__device__ float g_h[2 * NSEQ * HSZ];                       // finals only (s==29)
__device__ float g_xg[(size_t)2 * T_STEPS * 40 * 128 * 1024]; // [dir][t][mt][row][c']

// ---------------- helpers ----------------
__device__ __forceinline__ uint32_t smem_u32(const void* p) {
    uint32_t a;
    asm("{ .reg .u64 t; cvta.to.shared.u64 t, %1; cvt.u32.u64 %0, t; }" : "=r"(a) : "l"(p));
    return a;
}
__device__ __forceinline__ void cpa16(uint32_t dst, const void* src) {
    asm volatile("cp.async.cg.shared.global [%0], [%1], 16;" :: "r"(dst), "l"(src));
}
#define CP_COMMIT() asm volatile("cp.async.commit_group;" ::: "memory")
#define CP_WAIT2()  asm volatile("cp.async.wait_group 2;" ::: "memory")
#define CP_WAIT1()  asm volatile("cp.async.wait_group 1;" ::: "memory")
#define CP_WAIT0()  asm volatile("cp.async.wait_group 0;" ::: "memory")

__device__ __forceinline__ void ldm_x4(uint32_t* r, uint32_t addr) {
    asm volatile("ldmatrix.sync.aligned.m8n8.x4.shared.b16 {%0,%1,%2,%3}, [%4];"
                 : "=r"(r[0]), "=r"(r[1]), "=r"(r[2]), "=r"(r[3]) : "r"(addr));
}
__device__ __forceinline__ void mma16816(float* d, const uint32_t* a, uint32_t b0, uint32_t b1) {
    asm volatile(
        "mma.sync.aligned.m16n8k16.row.col.f32.bf16.bf16.f32 "
        "{%0,%1,%2,%3}, {%4,%5,%6,%7}, {%8,%9}, {%0,%1,%2,%3};"
        : "+f"(d[0]), "+f"(d[1]), "+f"(d[2]), "+f"(d[3])
        : "r"(a[0]), "r"(a[1]), "r"(a[2]), "r"(a[3]), "r"(b0), "r"(b1));
}
// 128B-row swizzle (8 x 16B chunks per row)
__device__ __forceinline__ uint32_t swz128(int row, int ch) {
    return (uint32_t)(row * 128 + ((ch ^ (row & 7)) << 4));
}
// 64B-row swizzle (4 x 16B chunks per row)
__device__ __forceinline__ uint32_t swz64(int row, int ch) {
    return (uint32_t)(row * 64 + ((ch ^ ((row >> 1) & 3)) << 4));
}
__device__ __forceinline__ float fsigm(float x) {
    float e;
    asm("ex2.approx.f32 %0, %1;" : "=f"(e) : "f"(x * -1.4426950408889634f));
    float r;
    asm("rcp.approx.f32 %0, %1;" : "=f"(r) : "f"(1.0f + e));
    return r;
}
__device__ __forceinline__ float ftanh(float x) { return fmaf(2.0f, fsigm(2.0f * x), -1.0f); }
__device__ __forceinline__ void split_bf(float v, uint16_t& hi_b, uint16_t& lo_b) {
    __nv_bfloat16 h = __float2bfloat16(v);
    float hf = __bfloat162float(h);
    memcpy(&hi_b, &h, 2);
    __nv_bfloat16 l = __float2bfloat16(v - hf);
    memcpy(&lo_b, &l, 2);
}

// ---------------- merged prepack (ONE launch) ----------------
#define SEG_BIAS 2048
#define SEG_W    (2 * 8 * 128 * 384)
#define SEG_X    (T_STEPS * NSEQ * 128)
#define SEG_HC   (2 * NSEQ * HSZ)
#define PRE_TOT  (SEG_BIAS + SEG_W + SEG_X + SEG_HC)

__global__ void prepack_all(const float* __restrict__ x,
                            const float* __restrict__ h0, const float* __restrict__ c0,
                            const float* __restrict__ Wih_f, const float* __restrict__ Whh_f,
                            const float* __restrict__ bih_f, const float* __restrict__ bhh_f,
                            const float* __restrict__ Wih_b, const float* __restrict__ Whh_b,
                            const float* __restrict__ bih_b, const float* __restrict__ bhh_b) {
    int idx = blockIdx.x * blockDim.x + threadIdx.x;
    if (idx < SEG_BIAS) {
        int c = idx & 1023, dir = idx >> 10;
        int h = c >> 2, g = c & 3;
        int row = g * HSZ + h;
        g_bias[dir][c] = dir ? (bih_b[row] + bhh_b[row]) : (bih_f[row] + bhh_f[row]);
        return;
    }
    idx -= SEG_BIAS;
    if (idx < SEG_W) {
        int k = idx % 384;
        int rest = idx / 384;
        int c = rest & 127;
        rest >>= 7;
        int nt = rest & 7;
        int dir = rest >> 3;
        const float* Wih = dir ? Wih_b : Wih_f;
        const float* Whh = dir ? Whh_b : Whh_f;
        int hg = nt * 32 + (c >> 2);
        int g = c & 3;
        int row = g * HSZ + hg;
        uint16_t hb, lb;
        if (k < 128) {
            float v = (k < ISZ) ? Wih[(size_t)row * ISZ + k] : 0.0f;
            split_bf(v, hb, lb);
            memcpy(&g_Bx[dir][nt][0][c][k], &hb, 2);
            memcpy(&g_Bx[dir][nt][1][c][k], &lb, 2);
        } else {
            float v = Whh[(size_t)row * HSZ + (k - 128)];
            split_bf(v, hb, lb);
            memcpy(&g_Bh[dir][nt][0][c][k - 128], &hb, 2);
            memcpy(&g_Bh[dir][nt][1][c][k - 128], &lb, 2);
        }
        return;
    }
    idx -= SEG_W;
    if (idx < SEG_X) {
        int k = idx & 127;
        int n = (idx >> 7) % NSEQ;
        int t = idx / (NSEQ * 128);
        float v = (k < ISZ) ? x[((size_t)n * T_STEPS + t) * ISZ + k] : 0.0f;
        uint16_t hb, lb; split_bf(v, hb, lb);
        int mt = n >> 7, m = n & 127;
        memcpy(&g_Ax[t][mt][0][m][k], &hb, 2);
        memcpy(&g_Ax[t][mt][1][m][k], &lb, 2);
        return;
    }
    idx -= SEG_X;
    if (idx < SEG_HC) {
        g_c[idx] = c0[idx];
        int k = idx & 255;
        int n = (idx >> 8) % NSEQ;
        int d = idx / (NSEQ * HSZ);
        float v = h0[idx];
        uint16_t hb, lb; split_bf(v, hb, lb);
        int mt = n >> 7, m = n & 127;
        memcpy(&g_Ah[0][d][mt][0][m][k], &hb, 2);
        memcpy(&g_Ah[0][d][mt][1][m][k], &lb, 2);
    }
}

// ---------------- xg GEMM v3: N=64 tiles, B-resident 32KB, 3-stage A, dist-2 ----------------
// smem: B resident 32KB (8 blocks [kq2+img? -> (kq*2+img)*4096] of [c64][k32]) @0
//       A stages 3 x 16KB @32768  ([img][row128][k32])
#define XG_SMEM (32768 + 3 * 16384)   // 81920
#define QTOT    (T_STEPS * 4)         // 120 k-quarter chunks

__global__ void __launch_bounds__(256, 2) xg_gemm(void) {
    extern __shared__ __align__(16) unsigned char smem[];
    const uint32_t sbase = smem_u32(smem);
    const int tid = threadIdx.x, wid = tid >> 5, lane = tid & 31;
    const int wm = wid & 3, wn = wid >> 2;   // warp tile: 32 rows x 32 cols
    const int nt = blockIdx.x;               // 16 tiles of 64 cols
    const int mt = blockIdx.y, dir = blockIdx.z;

    // bias -> regs
    float breg[4][2];
#pragma unroll
    for (int nj = 0; nj < 4; nj++) {
        const int c = wn * 32 + nj * 8 + (lane & 3) * 2;
        breg[nj][0] = g_bias[dir][nt * 64 + c];
        breg[nj][1] = g_bias[dir][nt * 64 + c + 1];
    }

    // load resident B (32KB): 8 blocks (kq 0..3, img 0..1) of [c 64][k 32]
    {
#pragma unroll
        for (int j = 0; j < 8; j++) {
            int id = tid + j * 256;
            int kq = id >> 9, img = (id >> 8) & 1, row = (id >> 2) & 63, ch = id & 3;
            cpa16(sbase + (kq * 2 + img) * 4096 + swz64(row, ch),
                  &g_Bx[dir][nt >> 1][img][(nt & 1) * 64 + row][kq * 32 + ch * 8]);
        }
    }
    CP_COMMIT();

    auto loadA = [&](int q) {   // q = t*4 + kq
        const int t = q >> 2, kq = q & 3;
        const uint32_t stg = sbase + 32768 + (q % 3) * 16384;
#pragma unroll
        for (int j = 0; j < 4; j++) {
            int id = tid + j * 256;
            int img = id >> 9, row = (id >> 2) & 127, ch = id & 3;
            cpa16(stg + img * 8192 + swz64(row, ch),
                  &g_Ax[t][mt][img][row][kq * 32 + ch * 8]);
        }
    };
    loadA(0); CP_COMMIT();
    loadA(1); CP_COMMIT();
    loadA(2); CP_COMMIT();

    float acc[2][4][4];
#pragma unroll
    for (int mi = 0; mi < 2; mi++)
#pragma unroll
        for (int nj = 0; nj < 4; nj++)
#pragma unroll
            for (int e = 0; e < 4; e++) acc[mi][nj][e] = 0.0f;

    for (int q = 0; q < QTOT; q++) {
        const int kq = q & 3;
        const int rem = QTOT - 1 - q;
        if (rem >= 2) CP_WAIT2(); else if (rem == 1) CP_WAIT1(); else CP_WAIT0();
        __syncthreads();

        const uint32_t astg = sbase + 32768 + (q % 3) * 16384;
        const uint32_t Ab0 = astg, Ab1 = astg + 8192;
        const uint32_t Bb0 = sbase + (kq * 2 + 0) * 4096;
        const uint32_t Bb1 = sbase + (kq * 2 + 1) * 4096;
#pragma unroll
        for (int ks = 0; ks < 2; ks++) {
            const int ac = 2 * ks + (lane >> 4);
            uint32_t ah[2][4], al[2][4], bh[2][4], bl[2][4];
#pragma unroll
            for (int fi = 0; fi < 2; fi++) {
                const int row = wm * 32 + fi * 16 + (lane & 15);
                const uint32_t off = swz64(row, ac);
                ldm_x4(ah[fi], Ab0 + off);
                ldm_x4(al[fi], Ab1 + off);
            }
#pragma unroll
            for (int gp = 0; gp < 2; gp++) {
                const int col = wn * 32 + gp * 16 + (lane & 15);
                const uint32_t off = swz64(col, ac);
                ldm_x4(bh[gp], Bb0 + off);
                ldm_x4(bl[gp], Bb1 + off);
            }
#pragma unroll
            for (int mi = 0; mi < 2; mi++)
#pragma unroll
                for (int gp = 0; gp < 2; gp++)
#pragma unroll
                    for (int sub = 0; sub < 2; sub++) {
                        float* d = acc[mi][gp * 2 + sub];
                        mma16816(d, ah[mi], bh[gp][sub], bh[gp][sub + 2]);
                        mma16816(d, ah[mi], bl[gp][sub], bl[gp][sub + 2]);
                        mma16816(d, al[mi], bh[gp][sub], bh[gp][sub + 2]);
                    }
        }
        __syncthreads();
        if (q + 3 < QTOT) { loadA(q + 3); CP_COMMIT(); }

        if (kq == 3) {
            // finished t = q>>2: store with bias, reset acc
            const int t = q >> 2;
            float* xgp = g_xg + (((size_t)(dir * T_STEPS + t) * 40 + mt) * 128) * 1024 + nt * 64;
#pragma unroll
            for (int mi = 0; mi < 2; mi++)
#pragma unroll
                for (int nj = 0; nj < 4; nj++) {
                    const int r = wm * 32 + mi * 16 + (lane >> 2);
                    const int c = wn * 32 + nj * 8 + (lane & 3) * 2;
                    float2 v0 = { acc[mi][nj][0] + breg[nj][0], acc[mi][nj][1] + breg[nj][1] };
                    float2 v1 = { acc[mi][nj][2] + breg[nj][0], acc[mi][nj][3] + breg[nj][1] };
                    *(float2*)&xgp[(size_t)r * 1024 + c] = v0;
                    *(float2*)&xgp[(size_t)(r + 8) * 1024 + c] = v1;
#pragma unroll
                    for (int e = 0; e < 4; e++) acc[mi][nj][e] = 0.0f;
                }
        }
    }
}

// ---------------- LSTM step: K=256 over 8 chunks of 32, 3-stage, dist-2, 2 CTAs/SM ----
// stage 32KB: Aimg0 8K | Aimg1 8K | Bimg0 8K | Bimg1 8K; 3 stages = 96KB.
// epilogue C (128 x 132 f32 = 67584B) overlays stages -> smem high-water 98304.
#define ST_SZ    32768
#define SM_TOTAL (3 * ST_SZ)   // 98304

__global__ void __launch_bounds__(256, 2) lstm_step_mma(int s) {
    extern __shared__ __align__(16) unsigned char smem[];
    const uint32_t sbase = smem_u32(smem);
    const int tid = threadIdx.x, wid = tid >> 5, lane = tid & 31;
    const int wm = wid & 3, wn = wid >> 2;
    const int nt = blockIdx.x, mt = blockIdx.y, dir = blockIdx.z;
    const int t = dir ? (T_STEPS - 1 - s) : s;
    const int par = s & 1;

    const __nv_bfloat16* Ap = &g_Ah[par][dir][mt][0][0][0];
    const __nv_bfloat16* Bp = &g_Bh[dir][nt][0][0][0];

    auto load_chunk = [&](int ck) {
        const uint32_t stg = sbase + (ck % 3) * ST_SZ;
#pragma unroll
        for (int j = 0; j < 4; j++) {
            int id = tid + j * 256;
            int img = id >> 9, row = (id >> 2) & 127, ch = id & 3;
            cpa16(stg + img * 8192 + swz64(row, ch),
                  &Ap[(size_t)img * 32768 + row * 256 + ck * 32 + ch * 8]);
        }
#pragma unroll
        for (int j = 0; j < 4; j++) {
            int id = tid + j * 256;
            int img = id >> 9, row = (id >> 2) & 127, ch = id & 3;
            cpa16(stg + 16384 + img * 8192 + swz64(row, ch),
                  &Bp[(size_t)img * 32768 + row * 256 + ck * 32 + ch * 8]);
        }
    };

    load_chunk(0); CP_COMMIT();
    load_chunk(1); CP_COMMIT();
    load_chunk(2); CP_COMMIT();

    // accumulator init from precomputed xg (+bias folded) — overlaps prologue loads
    const float* xgp = g_xg + (((size_t)(dir * T_STEPS + t) * 40 + mt) * 128) * 1024 + nt * 128;
    float acc[2][8][4];
#pragma unroll
    for (int mi = 0; mi < 2; mi++)
#pragma unroll
        for (int nj = 0; nj < 8; nj++) {
            const int r = wm * 32 + mi * 16 + (lane >> 2);
            const int c = wn * 64 + nj * 8 + (lane & 3) * 2;
            float2 v0 = *(const float2*)&xgp[(size_t)r * 1024 + c];
            float2 v1 = *(const float2*)&xgp[(size_t)(r + 8) * 1024 + c];
            acc[mi][nj][0] = v0.x; acc[mi][nj][1] = v0.y;
            acc[mi][nj][2] = v1.x; acc[mi][nj][3] = v1.y;
        }

    for (int ck = 0; ck < 8; ck++) {
        if (ck <= 5) CP_WAIT2(); else if (ck == 6) CP_WAIT1(); else CP_WAIT0();
        __syncthreads();

        const uint32_t stg = sbase + (ck % 3) * ST_SZ;
        const uint32_t Ab0 = stg, Ab1 = stg + 8192;
        const uint32_t Bb0 = stg + 16384, Bb1 = stg + 24576;
#pragma unroll
        for (int ks = 0; ks < 2; ks++) {
            const int ac = 2 * ks + (lane >> 4);
            uint32_t ah[2][4], al[2][4];
#pragma unroll
            for (int fi = 0; fi < 2; fi++) {
                const int row = wm * 32 + fi * 16 + (lane & 15);
                const uint32_t off = swz64(row, ac);
                ldm_x4(ah[fi], Ab0 + off);
                ldm_x4(al[fi], Ab1 + off);
            }
#pragma unroll
            for (int gph = 0; gph < 2; gph++) {
                uint32_t bh2[2][4], bl2[2][4];
#pragma unroll
                for (int gi = 0; gi < 2; gi++) {
                    const int col = wn * 64 + (gph * 2 + gi) * 16 + (lane & 15);
                    const uint32_t off = swz64(col, ac);
                    ldm_x4(bh2[gi], Bb0 + off);
                    ldm_x4(bl2[gi], Bb1 + off);
                }
#pragma unroll
                for (int mi = 0; mi < 2; mi++)
#pragma unroll
                    for (int gi = 0; gi < 2; gi++)
#pragma unroll
                        for (int sub = 0; sub < 2; sub++) {
                            float* d = acc[mi][(gph * 2 + gi) * 2 + sub];
                            mma16816(d, ah[mi], bh2[gi][sub], bh2[gi][sub + 2]);
                            mma16816(d, ah[mi], bl2[gi][sub], bl2[gi][sub + 2]);
                            mma16816(d, al[mi], bh2[gi][sub], bh2[gi][sub + 2]);
                        }
            }
        }
        __syncthreads();
        if (ck + 3 < 8) { load_chunk(ck + 3); CP_COMMIT(); }
    }
    __syncthreads();

    // ---------------- epilogue: gates -> smem -> LSTM cell ----------------
    float* Csm = (float*)smem;
#pragma unroll
    for (int mi = 0; mi < 2; mi++)
#pragma unroll
        for (int nj = 0; nj < 8; nj++) {
            const int r = wm * 32 + mi * 16 + (lane >> 2);
            const int c = wn * 64 + nj * 8 + (lane & 3) * 2;
            float* p = Csm + r * 132 + c;
            p[0] = acc[mi][nj][0];
            p[1] = acc[mi][nj][1];
            float* q = Csm + (r + 8) * 132 + c;
            q[0] = acc[mi][nj][2];
            q[1] = acc[mi][nj][3];
        }
    __syncthreads();

    const int n_l = tid >> 1;
    const int halfh = tid & 1;
    const int n = mt * 128 + n_l;
    const size_t cbase = (size_t)dir * NSEQ * HSZ + (size_t)n * HSZ;
    uint16_t hb[16], lb[16];
#pragma unroll
    for (int i = 0; i < 16; i++) {
        const int h_l = halfh * 16 + i;
        const float4 gt = *(const float4*)&Csm[n_l * 132 + h_l * 4];
        const float iv = fsigm(gt.x);
        const float fv = fsigm(gt.y);
        const float gv = ftanh(gt.z);
        const float ov = fsigm(gt.w);
        const size_t ci = cbase + nt * 32 + h_l;
        const float cn = fv * g_c[ci] + iv * gv;
        g_c[ci] = cn;
        const float hv = ov * ftanh(cn);
        if (s == T_STEPS - 1) g_h[ci] = hv;
        split_bf(hv, hb[i], lb[i]);
    }
    {
        const int kcol = nt * 32 + halfh * 16;
        uint4 u0, u1;
        uint32_t* w;
        w = (uint32_t*)&u0;
#pragma unroll
        for (int q = 0; q < 4; q++) w[q] = (uint32_t)hb[q * 2] | ((uint32_t)hb[q * 2 + 1] << 16);
        w = (uint32_t*)&u1;
#pragma unroll
        for (int q = 0; q < 4; q++) w[q] = (uint32_t)hb[8 + q * 2] | ((uint32_t)hb[8 + q * 2 + 1] << 16);
        *(uint4*)&g_Ah[par ^ 1][dir][mt][0][n_l][kcol]     = u0;
        *(uint4*)&g_Ah[par ^ 1][dir][mt][0][n_l][kcol + 8] = u1;
        w = (uint32_t*)&u0;
#pragma unroll
        for (int q = 0; q < 4; q++) w[q] = (uint32_t)lb[q * 2] | ((uint32_t)lb[q * 2 + 1] << 16);
        w = (uint32_t*)&u1;
#pragma unroll
        for (int q = 0; q < 4; q++) w[q] = (uint32_t)lb[8 + q * 2] | ((uint32_t)lb[8 + q * 2 + 1] << 16);
        *(uint4*)&g_Ah[par ^ 1][dir][mt][1][n_l][kcol]     = u0;
        *(uint4*)&g_Ah[par ^ 1][dir][mt][1][n_l][kcol + 8] = u1;
    }
}

// ---------------- head ----------------
__global__ __launch_bounds__(256) void head_kernel(
    const float* __restrict__ W1, const float* __restrict__ b1,
    const float* __restrict__ W2, const float* __restrict__ b2,
    float* __restrict__ out)
{
    __shared__ float fea[2560];
    __shared__ float zp[4][64];
    __shared__ float zz[64];
    __shared__ float lg[5];

    const int b = blockIdx.x;
    const int tid = threadIdx.x;
    const float* __restrict__ hF = g_h;
    const float* __restrict__ hB = g_h + NSEQ * HSZ;

    for (int i = tid; i < 2560; i += 256) {
        const int slot = i >> 8;
        const int mcol = i & 255;
        const int n = b * 10 + slot;
        const float v = (mcol < 128) ? hF[(size_t)n * HSZ + mcol] : hB[(size_t)n * HSZ + mcol];
        fea[i] = v;
        out[2560 + (size_t)b * 2560 + i] = v;
    }
    __syncthreads();

    const int j = tid & 63;
    const int p = tid >> 6;
    float sum = 0.0f;
    const int k0 = p * 640;
    for (int k = k0; k < k0 + 640; k++) sum += fea[k] * W1[(size_t)j * 2560 + k];
    zp[p][j] = sum;
    __syncthreads();
    if (tid < 64) zz[tid] = zp[0][tid] + zp[1][tid] + zp[2][tid] + zp[3][tid] + b1[tid];
    __syncthreads();

    if (tid < 5) {
        float ss = b2[tid];
        for (int k = 0; k < 64; k++) ss += zz[k] * W2[tid * 64 + k];
        lg[tid] = ss;
    }
    __syncthreads();
    if (tid == 0) {
        float mx = lg[0];
        for (int k = 1; k < 5; k++) mx = fmaxf(mx, lg[k]);
        float e[5], se = 0.0f;
        for (int k = 0; k < 5; k++) { e[k] = expf(lg[k] - mx); se += e[k]; }
        for (int k = 0; k < 5; k++) out[(size_t)b * 5 + k] = e[k] / se;
    }
}

extern "C" void kernel_launch(void* const* d_in, const int* in_sizes, int n_in,
                              void* d_out, int out_size) {
    const float* x     = (const float*)d_in[0];
    const float* h0    = (const float*)d_in[1];
    const float* c0    = (const float*)d_in[2];
    const float* Wih_f = (const float*)d_in[3];
    const float* Whh_f = (const float*)d_in[4];
    const float* bih_f = (const float*)d_in[5];
    const float* bhh_f = (const float*)d_in[6];
    const float* Wih_b = (const float*)d_in[7];
    const float* Whh_b = (const float*)d_in[8];
    const float* bih_b = (const float*)d_in[9];
    const float* bhh_b = (const float*)d_in[10];
    const float* W1    = (const float*)d_in[11];
    const float* b1    = (const float*)d_in[12];
    const float* W2    = (const float*)d_in[13];
    const float* b2    = (const float*)d_in[14];
    float* out = (float*)d_out;

    cudaFuncSetAttribute(xg_gemm, cudaFuncAttributeMaxDynamicSharedMemorySize, XG_SMEM);
    cudaFuncSetAttribute(lstm_step_mma, cudaFuncAttributeMaxDynamicSharedMemorySize, SM_TOTAL);

    // launches: 0 prepack, 1 xg, 2.. steps -> ncu sample lands on a step
    prepack_all<<<(PRE_TOT + 255) / 256, 256>>>(x, h0, c0, Wih_f, Whh_f, bih_f, bhh_f,
                                                Wih_b, Whh_b, bih_b, bhh_b);
    xg_gemm<<<dim3(16, 40, 2), 256, XG_SMEM>>>();

    dim3 grid(8, 40, 2);
    for (int s = 0; s < T_STEPS; s++) {
        lstm_step_mma<<<grid, 256, SM_TOTAL>>>(s);
    }
    head_kernel<<<NBATCH, 256>>>(W1, b1, W2, b2, out);
}

// round 11
// speedup vs baseline: 1.2237x; 1.2237x over previous
#include <cuda_runtime.h>
#include <cuda_fp16.h>
#include <cstdint>
#include <cstring>
#include <math.h>

// ---------------- problem constants ----------------
#define T_STEPS 30
#define ISZ     100
#define HSZ     256
#define NSEQ    5120
#define NBATCH  512

// ---------------- device scratch (allocation-free rule) ----------------
// fp16 2-pass split: activations (A) carry hi+lo images; weights (B) hi only.
__device__ __half g_Ax[T_STEPS][40][2][128][128];   // [t][mt][img][row][k]  x, k pad 100->128
__device__ __half g_Ah[2][2][40][2][128][256];      // [par][dir][mt][img][row][k]
__device__ __half g_Bx[2][8][128][128];             // [dir][nt8][c'][k]  Wih, gate-interleaved, hi only
__device__ __half g_Bh[2][8][128][256];             // [dir][nt8][c'][k]  Whh, hi only
__device__ float g_bias[2][1024];                   // [dir][c'=h*4+g]
__device__ float g_c[2 * NSEQ * HSZ];
__device__ float g_h[2 * NSEQ * HSZ];               // finals only (s==29)
__device__ float g_xg[(size_t)2 * T_STEPS * 40 * 128 * 1024]; // [dir][t][mt][row][c']

// ---------------- helpers ----------------
__device__ __forceinline__ uint32_t smem_u32(const void* p) {
    uint32_t a;
    asm("{ .reg .u64 t; cvta.to.shared.u64 t, %1; cvt.u32.u64 %0, t; }" : "=r"(a) : "l"(p));
    return a;
}
__device__ __forceinline__ void cpa16(uint32_t dst, const void* src) {
    asm volatile("cp.async.cg.shared.global [%0], [%1], 16;" :: "r"(dst), "l"(src));
}
#define CP_COMMIT() asm volatile("cp.async.commit_group;" ::: "memory")
#define CP_WAIT2()  asm volatile("cp.async.wait_group 2;" ::: "memory")
#define CP_WAIT1()  asm volatile("cp.async.wait_group 1;" ::: "memory")
#define CP_WAIT0()  asm volatile("cp.async.wait_group 0;" ::: "memory")

__device__ __forceinline__ void ldm_x4(uint32_t* r, uint32_t addr) {
    asm volatile("ldmatrix.sync.aligned.m8n8.x4.shared.b16 {%0,%1,%2,%3}, [%4];"
                 : "=r"(r[0]), "=r"(r[1]), "=r"(r[2]), "=r"(r[3]) : "r"(addr));
}
__device__ __forceinline__ void mma16816(float* d, const uint32_t* a, uint32_t b0, uint32_t b1) {
    asm volatile(
        "mma.sync.aligned.m16n8k16.row.col.f32.f16.f16.f32 "
        "{%0,%1,%2,%3}, {%4,%5,%6,%7}, {%8,%9}, {%0,%1,%2,%3};"
        : "+f"(d[0]), "+f"(d[1]), "+f"(d[2]), "+f"(d[3])
        : "r"(a[0]), "r"(a[1]), "r"(a[2]), "r"(a[3]), "r"(b0), "r"(b1));
}
// 64B-row swizzle (4 x 16B chunks per row)
__device__ __forceinline__ uint32_t swz64(int row, int ch) {
    return (uint32_t)(row * 64 + ((ch ^ ((row >> 1) & 3)) << 4));
}
__device__ __forceinline__ float fsigm(float x) {
    float e;
    asm("ex2.approx.f32 %0, %1;" : "=f"(e) : "f"(x * -1.4426950408889634f));
    float r;
    asm("rcp.approx.f32 %0, %1;" : "=f"(r) : "f"(1.0f + e));
    return r;
}
__device__ __forceinline__ float ftanh(float x) { return fmaf(2.0f, fsigm(2.0f * x), -1.0f); }
__device__ __forceinline__ void split_h(float v, uint16_t& hi_b, uint16_t& lo_b) {
    __half h = __float2half_rn(v);
    float hf = __half2float(h);
    memcpy(&hi_b, &h, 2);
    __half l = __float2half_rn(v - hf);
    memcpy(&lo_b, &l, 2);
}

// ---------------- merged prepack (ONE launch) ----------------
#define SEG_BIAS 2048
#define SEG_W    (2 * 8 * 128 * 384)
#define SEG_X    (T_STEPS * NSEQ * 128)
#define SEG_HC   (2 * NSEQ * HSZ)
#define PRE_TOT  (SEG_BIAS + SEG_W + SEG_X + SEG_HC)

__global__ void prepack_all(const float* __restrict__ x,
                            const float* __restrict__ h0, const float* __restrict__ c0,
                            const float* __restrict__ Wih_f, const float* __restrict__ Whh_f,
                            const float* __restrict__ bih_f, const float* __restrict__ bhh_f,
                            const float* __restrict__ Wih_b, const float* __restrict__ Whh_b,
                            const float* __restrict__ bih_b, const float* __restrict__ bhh_b) {
    int idx = blockIdx.x * blockDim.x + threadIdx.x;
    if (idx < SEG_BIAS) {
        int c = idx & 1023, dir = idx >> 10;
        int h = c >> 2, g = c & 3;
        int row = g * HSZ + h;
        g_bias[dir][c] = dir ? (bih_b[row] + bhh_b[row]) : (bih_f[row] + bhh_f[row]);
        return;
    }
    idx -= SEG_BIAS;
    if (idx < SEG_W) {
        int k = idx % 384;
        int rest = idx / 384;
        int c = rest & 127;
        rest >>= 7;
        int nt = rest & 7;
        int dir = rest >> 3;
        const float* Wih = dir ? Wih_b : Wih_f;
        const float* Whh = dir ? Whh_b : Whh_f;
        int hg = nt * 32 + (c >> 2);
        int g = c & 3;
        int row = g * HSZ + hg;
        if (k < 128) {
            float v = (k < ISZ) ? Wih[(size_t)row * ISZ + k] : 0.0f;
            g_Bx[dir][nt][c][k] = __float2half_rn(v);
        } else {
            float v = Whh[(size_t)row * HSZ + (k - 128)];
            g_Bh[dir][nt][c][k - 128] = __float2half_rn(v);
        }
        return;
    }
    idx -= SEG_W;
    if (idx < SEG_X) {
        int k = idx & 127;
        int n = (idx >> 7) % NSEQ;
        int t = idx / (NSEQ * 128);
        float v = (k < ISZ) ? x[((size_t)n * T_STEPS + t) * ISZ + k] : 0.0f;
        uint16_t hb, lb; split_h(v, hb, lb);
        int mt = n >> 7, m = n & 127;
        memcpy(&g_Ax[t][mt][0][m][k], &hb, 2);
        memcpy(&g_Ax[t][mt][1][m][k], &lb, 2);
        return;
    }
    idx -= SEG_X;
    if (idx < SEG_HC) {
        g_c[idx] = c0[idx];
        int k = idx & 255;
        int n = (idx >> 8) % NSEQ;
        int d = idx / (NSEQ * HSZ);
        float v = h0[idx];
        uint16_t hb, lb; split_h(v, hb, lb);
        int mt = n >> 7, m = n & 127;
        memcpy(&g_Ah[0][d][mt][0][m][k], &hb, 2);
        memcpy(&g_Ah[0][d][mt][1][m][k], &lb, 2);
    }
}

// ---------------- xg GEMM: N=64 tiles, B-resident 16KB (hi), 3-stage A, dist-2 ----------------
// smem: B resident 16KB (4 blocks kq*4096 of [c64][k32]) @0 | A stages 3x16KB @16384 ([img][128][k32])
#define XG_SMEM (16384 + 3 * 16384)   // 65536
#define QTOT    (T_STEPS * 4)         // 120 k-quarter chunks

__global__ void __launch_bounds__(256, 2) xg_gemm(void) {
    extern __shared__ __align__(16) unsigned char smem[];
    const uint32_t sbase = smem_u32(smem);
    const int tid = threadIdx.x, wid = tid >> 5, lane = tid & 31;
    const int wm = wid & 3, wn = wid >> 2;   // warp tile: 32 rows x 32 cols
    const int nt = blockIdx.x;               // 16 tiles of 64 cols
    const int mt = blockIdx.y, dir = blockIdx.z;

    float breg[4][2];
#pragma unroll
    for (int nj = 0; nj < 4; nj++) {
        const int c = wn * 32 + nj * 8 + (lane & 3) * 2;
        breg[nj][0] = g_bias[dir][nt * 64 + c];
        breg[nj][1] = g_bias[dir][nt * 64 + c + 1];
    }

    // load resident B (16KB): 4 blocks (kq) of [c 64][k 32], hi only
    {
#pragma unroll
        for (int j = 0; j < 4; j++) {
            int id = tid + j * 256;
            int kq = id >> 8, row = (id >> 2) & 63, ch = id & 3;
            cpa16(sbase + kq * 4096 + swz64(row, ch),
                  &g_Bx[dir][nt >> 1][(nt & 1) * 64 + row][kq * 32 + ch * 8]);
        }
    }
    CP_COMMIT();

    auto loadA = [&](int q) {   // q = t*4 + kq
        const int t = q >> 2, kq = q & 3;
        const uint32_t stg = sbase + 16384 + (q % 3) * 16384;
#pragma unroll
        for (int j = 0; j < 4; j++) {
            int id = tid + j * 256;
            int img = id >> 9, row = (id >> 2) & 127, ch = id & 3;
            cpa16(stg + img * 8192 + swz64(row, ch),
                  &g_Ax[t][mt][img][row][kq * 32 + ch * 8]);
        }
    };
    loadA(0); CP_COMMIT();
    loadA(1); CP_COMMIT();
    loadA(2); CP_COMMIT();

    float acc[2][4][4];
#pragma unroll
    for (int mi = 0; mi < 2; mi++)
#pragma unroll
        for (int nj = 0; nj < 4; nj++)
#pragma unroll
            for (int e = 0; e < 4; e++) acc[mi][nj][e] = 0.0f;

    for (int q = 0; q < QTOT; q++) {
        const int kq = q & 3;
        const int rem = QTOT - 1 - q;
        if (rem >= 2) CP_WAIT2(); else if (rem == 1) CP_WAIT1(); else CP_WAIT0();
        __syncthreads();

        const uint32_t astg = sbase + 16384 + (q % 3) * 16384;
        const uint32_t Ab0 = astg, Ab1 = astg + 8192;
        const uint32_t Bb = sbase + kq * 4096;
#pragma unroll
        for (int ks = 0; ks < 2; ks++) {
            const int ac = 2 * ks + (lane >> 4);
            uint32_t ah[2][4], al[2][4], bh[2][4];
#pragma unroll
            for (int fi = 0; fi < 2; fi++) {
                const int row = wm * 32 + fi * 16 + (lane & 15);
                const uint32_t off = swz64(row, ac);
                ldm_x4(ah[fi], Ab0 + off);
                ldm_x4(al[fi], Ab1 + off);
            }
#pragma unroll
            for (int gp = 0; gp < 2; gp++) {
                const int col = wn * 32 + gp * 16 + (lane & 15);
                ldm_x4(bh[gp], Bb + swz64(col, ac));
            }
#pragma unroll
            for (int mi = 0; mi < 2; mi++)
#pragma unroll
                for (int gp = 0; gp < 2; gp++)
#pragma unroll
                    for (int sub = 0; sub < 2; sub++) {
                        float* d = acc[mi][gp * 2 + sub];
                        mma16816(d, ah[mi], bh[gp][sub], bh[gp][sub + 2]);
                        mma16816(d, al[mi], bh[gp][sub], bh[gp][sub + 2]);
                    }
        }
        __syncthreads();
        if (q + 3 < QTOT) { loadA(q + 3); CP_COMMIT(); }

        if (kq == 3) {
            const int t = q >> 2;
            float* xgp = g_xg + (((size_t)(dir * T_STEPS + t) * 40 + mt) * 128) * 1024 + nt * 64;
#pragma unroll
            for (int mi = 0; mi < 2; mi++)
#pragma unroll
                for (int nj = 0; nj < 4; nj++) {
                    const int r = wm * 32 + mi * 16 + (lane >> 2);
                    const int c = wn * 32 + nj * 8 + (lane & 3) * 2;
                    float2 v0 = { acc[mi][nj][0] + breg[nj][0], acc[mi][nj][1] + breg[nj][1] };
                    float2 v1 = { acc[mi][nj][2] + breg[nj][0], acc[mi][nj][3] + breg[nj][1] };
                    *(float2*)&xgp[(size_t)r * 1024 + c] = v0;
                    *(float2*)&xgp[(size_t)(r + 8) * 1024 + c] = v1;
#pragma unroll
                    for (int e = 0; e < 4; e++) acc[mi][nj][e] = 0.0f;
                }
        }
    }
}

// ---------------- LSTM step: K=256, 8 chunks of 32, 2-stage, 2 CTAs/SM, fp16 2-pass ----
// stage 24KB: A_hi 8K | A_lo 8K | B 8K; 2 stages = 48KB.
// epilogue C (128 x 132 f32 = 67584B) overlays stages -> smem high-water 67584.
#define ST_SZ    24576
#define SM_TOTAL 67584

__global__ void __launch_bounds__(256, 2) lstm_step_mma(int s) {
    extern __shared__ __align__(16) unsigned char smem[];
    const uint32_t sbase = smem_u32(smem);
    const int tid = threadIdx.x, wid = tid >> 5, lane = tid & 31;
    const int wm = wid & 3, wn = wid >> 2;
    const int nt = blockIdx.x, mt = blockIdx.y, dir = blockIdx.z;
    const int t = dir ? (T_STEPS - 1 - s) : s;
    const int par = s & 1;

    const __half* Ap = &g_Ah[par][dir][mt][0][0][0];
    const __half* Bp = &g_Bh[dir][nt][0][0];

    auto load_chunk = [&](int ck) {
        const uint32_t stg = sbase + (ck & 1) * ST_SZ;
#pragma unroll
        for (int j = 0; j < 4; j++) {
            int id = tid + j * 256;
            int img = id >> 9, row = (id >> 2) & 127, ch = id & 3;
            cpa16(stg + img * 8192 + swz64(row, ch),
                  &Ap[(size_t)img * 32768 + row * 256 + ck * 32 + ch * 8]);
        }
#pragma unroll
        for (int j = 0; j < 2; j++) {
            int id = tid + j * 256;
            int row = (id >> 2) & 127, ch = id & 3;
            cpa16(stg + 16384 + swz64(row, ch),
                  &Bp[(size_t)row * 256 + ck * 32 + ch * 8]);
        }
    };

    load_chunk(0); CP_COMMIT();
    load_chunk(1); CP_COMMIT();

    // accumulator init from precomputed xg (+bias folded) — overlaps prologue loads
    const float* xgp = g_xg + (((size_t)(dir * T_STEPS + t) * 40 + mt) * 128) * 1024 + nt * 128;
    float acc[2][8][4];
#pragma unroll
    for (int mi = 0; mi < 2; mi++)
#pragma unroll
        for (int nj = 0; nj < 8; nj++) {
            const int r = wm * 32 + mi * 16 + (lane >> 2);
            const int c = wn * 64 + nj * 8 + (lane & 3) * 2;
            float2 v0 = *(const float2*)&xgp[(size_t)r * 1024 + c];
            float2 v1 = *(const float2*)&xgp[(size_t)(r + 8) * 1024 + c];
            acc[mi][nj][0] = v0.x; acc[mi][nj][1] = v0.y;
            acc[mi][nj][2] = v1.x; acc[mi][nj][3] = v1.y;
        }

    for (int ck = 0; ck < 8; ck++) {
        if (ck < 7) CP_WAIT1(); else CP_WAIT0();
        __syncthreads();

        const uint32_t stg = sbase + (ck & 1) * ST_SZ;
        const uint32_t Ab0 = stg, Ab1 = stg + 8192;
        const uint32_t Bb = stg + 16384;
#pragma unroll
        for (int ks = 0; ks < 2; ks++) {
            const int ac = 2 * ks + (lane >> 4);
            uint32_t ah[2][4], al[2][4];
#pragma unroll
            for (int fi = 0; fi < 2; fi++) {
                const int row = wm * 32 + fi * 16 + (lane & 15);
                const uint32_t off = swz64(row, ac);
                ldm_x4(ah[fi], Ab0 + off);
                ldm_x4(al[fi], Ab1 + off);
            }
#pragma unroll
            for (int gph = 0; gph < 2; gph++) {
                uint32_t bh2[2][4];
#pragma unroll
                for (int gi = 0; gi < 2; gi++) {
                    const int col = wn * 64 + (gph * 2 + gi) * 16 + (lane & 15);
                    ldm_x4(bh2[gi], Bb + swz64(col, ac));
                }
#pragma unroll
                for (int mi = 0; mi < 2; mi++)
#pragma unroll
                    for (int gi = 0; gi < 2; gi++)
#pragma unroll
                        for (int sub = 0; sub < 2; sub++) {
                            float* d = acc[mi][(gph * 2 + gi) * 2 + sub];
                            mma16816(d, ah[mi], bh2[gi][sub], bh2[gi][sub + 2]);
                            mma16816(d, al[mi], bh2[gi][sub], bh2[gi][sub + 2]);
                        }
            }
        }
        __syncthreads();
        if (ck + 2 < 8) { load_chunk(ck + 2); CP_COMMIT(); }
    }
    __syncthreads();

    // ---------------- epilogue: gates -> smem -> LSTM cell ----------------
    float* Csm = (float*)smem;
#pragma unroll
    for (int mi = 0; mi < 2; mi++)
#pragma unroll
        for (int nj = 0; nj < 8; nj++) {
            const int r = wm * 32 + mi * 16 + (lane >> 2);
            const int c = wn * 64 + nj * 8 + (lane & 3) * 2;
            float* p = Csm + r * 132 + c;
            p[0] = acc[mi][nj][0];
            p[1] = acc[mi][nj][1];
            float* q = Csm + (r + 8) * 132 + c;
            q[0] = acc[mi][nj][2];
            q[1] = acc[mi][nj][3];
        }
    __syncthreads();

    const int n_l = tid >> 1;
    const int halfh = tid & 1;
    const int n = mt * 128 + n_l;
    const size_t cbase = (size_t)dir * NSEQ * HSZ + (size_t)n * HSZ;
    uint16_t hb[16], lb[16];
#pragma unroll
    for (int i = 0; i < 16; i++) {
        const int h_l = halfh * 16 + i;
        const float4 gt = *(const float4*)&Csm[n_l * 132 + h_l * 4];
        const float iv = fsigm(gt.x);
        const float fv = fsigm(gt.y);
        const float gv = ftanh(gt.z);
        const float ov = fsigm(gt.w);
        const size_t ci = cbase + nt * 32 + h_l;
        const float cn = fv * g_c[ci] + iv * gv;
        g_c[ci] = cn;
        const float hv = ov * ftanh(cn);
        if (s == T_STEPS - 1) g_h[ci] = hv;
        split_h(hv, hb[i], lb[i]);
    }
    {
        const int kcol = nt * 32 + halfh * 16;
        uint4 u0, u1;
        uint32_t* w;
        w = (uint32_t*)&u0;
#pragma unroll
        for (int q = 0; q < 4; q++) w[q] = (uint32_t)hb[q * 2] | ((uint32_t)hb[q * 2 + 1] << 16);
        w = (uint32_t*)&u1;
#pragma unroll
        for (int q = 0; q < 4; q++) w[q] = (uint32_t)hb[8 + q * 2] | ((uint32_t)hb[8 + q * 2 + 1] << 16);
        *(uint4*)&g_Ah[par ^ 1][dir][mt][0][n_l][kcol]     = u0;
        *(uint4*)&g_Ah[par ^ 1][dir][mt][0][n_l][kcol + 8] = u1;
        w = (uint32_t*)&u0;
#pragma unroll
        for (int q = 0; q < 4; q++) w[q] = (uint32_t)lb[q * 2] | ((uint32_t)lb[q * 2 + 1] << 16);
        w = (uint32_t*)&u1;
#pragma unroll
        for (int q = 0; q < 4; q++) w[q] = (uint32_t)lb[8 + q * 2] | ((uint32_t)lb[8 + q * 2 + 1] << 16);
        *(uint4*)&g_Ah[par ^ 1][dir][mt][1][n_l][kcol]     = u0;
        *(uint4*)&g_Ah[par ^ 1][dir][mt][1][n_l][kcol + 8] = u1;
    }
}

// ---------------- head ----------------
__global__ __launch_bounds__(256) void head_kernel(
    const float* __restrict__ W1, const float* __restrict__ b1,
    const float* __restrict__ W2, const float* __restrict__ b2,
    float* __restrict__ out)
{
    __shared__ float fea[2560];
    __shared__ float zp[4][64];
    __shared__ float zz[64];
    __shared__ float lg[5];

    const int b = blockIdx.x;
    const int tid = threadIdx.x;
    const float* __restrict__ hF = g_h;
    const float* __restrict__ hB = g_h + NSEQ * HSZ;

    for (int i = tid; i < 2560; i += 256) {
        const int slot = i >> 8;
        const int mcol = i & 255;
        const int n = b * 10 + slot;
        const float v = (mcol < 128) ? hF[(size_t)n * HSZ + mcol] : hB[(size_t)n * HSZ + mcol];
        fea[i] = v;
        out[2560 + (size_t)b * 2560 + i] = v;
    }
    __syncthreads();

    const int j = tid & 63;
    const int p = tid >> 6;
    float sum = 0.0f;
    const int k0 = p * 640;
    for (int k = k0; k < k0 + 640; k++) sum += fea[k] * W1[(size_t)j * 2560 + k];
    zp[p][j] = sum;
    __syncthreads();
    if (tid < 64) zz[tid] = zp[0][tid] + zp[1][tid] + zp[2][tid] + zp[3][tid] + b1[tid];
    __syncthreads();

    if (tid < 5) {
        float ss = b2[tid];
        for (int k = 0; k < 64; k++) ss += zz[k] * W2[tid * 64 + k];
        lg[tid] = ss;
    }
    __syncthreads();
    if (tid == 0) {
        float mx = lg[0];
        for (int k = 1; k < 5; k++) mx = fmaxf(mx, lg[k]);
        float e[5], se = 0.0f;
        for (int k = 0; k < 5; k++) { e[k] = expf(lg[k] - mx); se += e[k]; }
        for (int k = 0; k < 5; k++) out[(size_t)b * 5 + k] = e[k] / se;
    }
}

extern "C" void kernel_launch(void* const* d_in, const int* in_sizes, int n_in,
                              void* d_out, int out_size) {
    const float* x     = (const float*)d_in[0];
    const float* h0    = (const float*)d_in[1];
    const float* c0    = (const float*)d_in[2];
    const float* Wih_f = (const float*)d_in[3];
    const float* Whh_f = (const float*)d_in[4];
    const float* bih_f = (const float*)d_in[5];
    const float* bhh_f = (const float*)d_in[6];
    const float* Wih_b = (const float*)d_in[7];
    const float* Whh_b = (const float*)d_in[8];
    const float* bih_b = (const float*)d_in[9];
    const float* bhh_b = (const float*)d_in[10];
    const float* W1    = (const float*)d_in[11];
    const float* b1    = (const float*)d_in[12];
    const float* W2    = (const float*)d_in[13];
    const float* b2    = (const float*)d_in[14];
    float* out = (float*)d_out;

    cudaFuncSetAttribute(xg_gemm, cudaFuncAttributeMaxDynamicSharedMemorySize, XG_SMEM);
    cudaFuncSetAttribute(lstm_step_mma, cudaFuncAttributeMaxDynamicSharedMemorySize, SM_TOTAL);

    // launches: 0 prepack, 1 xg, 2.. steps -> ncu sample lands on a step
    prepack_all<<<(PRE_TOT + 255) / 256, 256>>>(x, h0, c0, Wih_f, Whh_f, bih_f, bhh_f,
                                                Wih_b, Whh_b, bih_b, bhh_b);
    xg_gemm<<<dim3(16, 40, 2), 256, XG_SMEM>>>();

    dim3 grid(8, 40, 2);
    for (int s = 0; s < T_STEPS; s++) {
        lstm_step_mma<<<grid, 256, SM_TOTAL>>>(s);
    }
    head_kernel<<<NBATCH, 256>>>(W1, b1, W2, b2, out);
}

// round 12
// speedup vs baseline: 1.3114x; 1.0717x over previous
#include <cuda_runtime.h>
#include <cuda_fp16.h>
#include <cstdint>
#include <cstring>
#include <math.h>

// ---------------- problem constants ----------------
#define T_STEPS 30
#define ISZ     100
#define HSZ     256
#define NSEQ    5120
#define NBATCH  512

// ---------------- device scratch (allocation-free rule) ----------------
// fp16 2-pass split: activations (A) carry hi+lo images; weights (B) hi only.
__device__ __half g_Ax[T_STEPS][40][2][128][128];   // [t][mt][img][row][k]  x, k pad 100->128
__device__ __half g_Ah[2][2][40][2][128][256];      // [par][dir][mt][img][row][k]
__device__ __half g_Bx[2][8][128][128];             // [dir][nt8][c'][k]  Wih, gate-interleaved, hi only
__device__ __half g_Bh[2][8][128][256];             // [dir][nt8][c'][k]  Whh, hi only
__device__ float g_bias[2][1024];                   // [dir][c'=h*4+g]
// c-state in MMA-fragment layout: [dir][mt][nt][wid][lane][mi*8+nj] (16 floats per thread)
__device__ float g_cfrag[(size_t)2 * 40 * 8 * 8 * 32 * 16];
__device__ float g_h[2 * NSEQ * HSZ];               // finals only (s==29), standard layout
__device__ float g_xg[(size_t)2 * T_STEPS * 40 * 128 * 1024]; // [dir][t][mt][row][c']

// ---------------- helpers ----------------
__device__ __forceinline__ uint32_t smem_u32(const void* p) {
    uint32_t a;
    asm("{ .reg .u64 t; cvta.to.shared.u64 t, %1; cvt.u32.u64 %0, t; }" : "=r"(a) : "l"(p));
    return a;
}
__device__ __forceinline__ void cpa16(uint32_t dst, const void* src) {
    asm volatile("cp.async.cg.shared.global [%0], [%1], 16;" :: "r"(dst), "l"(src));
}
#define CP_COMMIT() asm volatile("cp.async.commit_group;" ::: "memory")
#define CP_WAIT2()  asm volatile("cp.async.wait_group 2;" ::: "memory")
#define CP_WAIT1()  asm volatile("cp.async.wait_group 1;" ::: "memory")
#define CP_WAIT0()  asm volatile("cp.async.wait_group 0;" ::: "memory")

__device__ __forceinline__ void ldm_x4(uint32_t* r, uint32_t addr) {
    asm volatile("ldmatrix.sync.aligned.m8n8.x4.shared.b16 {%0,%1,%2,%3}, [%4];"
                 : "=r"(r[0]), "=r"(r[1]), "=r"(r[2]), "=r"(r[3]) : "r"(addr));
}
__device__ __forceinline__ void mma16816(float* d, const uint32_t* a, uint32_t b0, uint32_t b1) {
    asm volatile(
        "mma.sync.aligned.m16n8k16.row.col.f32.f16.f16.f32 "
        "{%0,%1,%2,%3}, {%4,%5,%6,%7}, {%8,%9}, {%0,%1,%2,%3};"
        : "+f"(d[0]), "+f"(d[1]), "+f"(d[2]), "+f"(d[3])
        : "r"(a[0]), "r"(a[1]), "r"(a[2]), "r"(a[3]), "r"(b0), "r"(b1));
}
// 64B-row swizzle (4 x 16B chunks per row)
__device__ __forceinline__ uint32_t swz64(int row, int ch) {
    return (uint32_t)(row * 64 + ((ch ^ ((row >> 1) & 3)) << 4));
}
__device__ __forceinline__ float fsigm(float x) {
    float e;
    asm("ex2.approx.f32 %0, %1;" : "=f"(e) : "f"(x * -1.4426950408889634f));
    float r;
    asm("rcp.approx.f32 %0, %1;" : "=f"(r) : "f"(1.0f + e));
    return r;
}
__device__ __forceinline__ float ftanh(float x) { return fmaf(2.0f, fsigm(2.0f * x), -1.0f); }
__device__ __forceinline__ void split_h(float v, uint16_t& hi_b, uint16_t& lo_b) {
    __half h = __float2half_rn(v);
    float hf = __half2float(h);
    memcpy(&hi_b, &h, 2);
    __half l = __float2half_rn(v - hf);
    memcpy(&lo_b, &l, 2);
}

// ---------------- merged prepack (ONE launch) ----------------
#define SEG_BIAS 2048
#define SEG_W    (2 * 8 * 128 * 384)
#define SEG_X    (T_STEPS * NSEQ * 128)
#define SEG_HC   (2 * NSEQ * HSZ)
#define PRE_TOT  (SEG_BIAS + SEG_W + SEG_X + SEG_HC)

__global__ void prepack_all(const float* __restrict__ x,
                            const float* __restrict__ h0, const float* __restrict__ c0,
                            const float* __restrict__ Wih_f, const float* __restrict__ Whh_f,
                            const float* __restrict__ bih_f, const float* __restrict__ bhh_f,
                            const float* __restrict__ Wih_b, const float* __restrict__ Whh_b,
                            const float* __restrict__ bih_b, const float* __restrict__ bhh_b) {
    int idx = blockIdx.x * blockDim.x + threadIdx.x;
    if (idx < SEG_BIAS) {
        int c = idx & 1023, dir = idx >> 10;
        int h = c >> 2, g = c & 3;
        int row = g * HSZ + h;
        g_bias[dir][c] = dir ? (bih_b[row] + bhh_b[row]) : (bih_f[row] + bhh_f[row]);
        return;
    }
    idx -= SEG_BIAS;
    if (idx < SEG_W) {
        int k = idx % 384;
        int rest = idx / 384;
        int c = rest & 127;
        rest >>= 7;
        int nt = rest & 7;
        int dir = rest >> 3;
        const float* Wih = dir ? Wih_b : Wih_f;
        const float* Whh = dir ? Whh_b : Whh_f;
        int hg = nt * 32 + (c >> 2);
        int g = c & 3;
        int row = g * HSZ + hg;
        if (k < 128) {
            float v = (k < ISZ) ? Wih[(size_t)row * ISZ + k] : 0.0f;
            g_Bx[dir][nt][c][k] = __float2half_rn(v);
        } else {
            float v = Whh[(size_t)row * HSZ + (k - 128)];
            g_Bh[dir][nt][c][k - 128] = __float2half_rn(v);
        }
        return;
    }
    idx -= SEG_W;
    if (idx < SEG_X) {
        int k = idx & 127;
        int n = (idx >> 7) % NSEQ;
        int t = idx / (NSEQ * 128);
        float v = (k < ISZ) ? x[((size_t)n * T_STEPS + t) * ISZ + k] : 0.0f;
        uint16_t hb, lb; split_h(v, hb, lb);
        int mt = n >> 7, m = n & 127;
        memcpy(&g_Ax[t][mt][0][m][k], &hb, 2);
        memcpy(&g_Ax[t][mt][1][m][k], &lb, 2);
        return;
    }
    idx -= SEG_X;
    if (idx < SEG_HC) {
        int k = idx & 255;
        int n = (idx >> 8) % NSEQ;
        int d = idx / (NSEQ * HSZ);
        // c0 -> fragment layout
        {
            int mt = n >> 7, row_l = n & 127;
            int nt = k >> 5, h_l = k & 31;
            int wm = row_l >> 5, mi = (row_l >> 4) & 1, rsub = row_l & 15;
            int wn = h_l >> 4, nj = (h_l & 15) >> 1, hbit = h_l & 1;
            int lane = ((rsub & 7) << 2) | (hbit << 1) | (rsub >> 3);
            int wid = wm | (wn << 2);
            size_t fidx = (((((size_t)d * 40 + mt) * 8 + nt) * 8 + wid) * 32 + lane) * 16
                          + mi * 8 + nj;
            g_cfrag[fidx] = c0[idx];
        }
        // h0 -> packed hi/lo images (parity 0)
        float v = h0[idx];
        uint16_t hb, lb; split_h(v, hb, lb);
        int mt = n >> 7, m = n & 127;
        memcpy(&g_Ah[0][d][mt][0][m][k], &hb, 2);
        memcpy(&g_Ah[0][d][mt][1][m][k], &lb, 2);
    }
}

// ---------------- xg GEMM: N=128 tiles, B-resident 32KB (hi), 3-stage A, dist-2 ----------
// smem: B 32KB (4 blocks kq*8192 of [c128][k32]) @0 | A stages 3x16KB @32768 | bias 512B @81920
#define XG_SMEM  (32768 + 3 * 16384 + 512)   // 82432
#define QTOT     (T_STEPS * 4)               // 120 k-quarter chunks

__global__ void __launch_bounds__(256, 2) xg_gemm(void) {
    extern __shared__ __align__(16) unsigned char smem[];
    const uint32_t sbase = smem_u32(smem);
    const int tid = threadIdx.x, wid = tid >> 5, lane = tid & 31;
    const int wm = wid & 3, wn = wid >> 2;   // warp tile: 32 rows x 64 cols
    const int nt = blockIdx.x;               // 8 tiles of 128 cols
    const int mt = blockIdx.y, dir = blockIdx.z;

    float* bias_sm = (float*)(smem + 81920);
    if (tid < 128) bias_sm[tid] = g_bias[dir][nt * 128 + tid];

    // load resident B (32KB): 4 blocks (kq) of [c 128][k 32], hi only
    {
#pragma unroll
        for (int j = 0; j < 8; j++) {
            int id = tid + j * 256;
            int kq = id >> 9, row = (id >> 2) & 127, ch = id & 3;
            cpa16(sbase + kq * 8192 + swz64(row, ch),
                  &g_Bx[dir][nt][row][kq * 32 + ch * 8]);
        }
    }
    CP_COMMIT();

    auto loadA = [&](int q) {   // q = t*4 + kq
        const int t = q >> 2, kq = q & 3;
        const uint32_t stg = sbase + 32768 + (q % 3) * 16384;
#pragma unroll
        for (int j = 0; j < 4; j++) {
            int id = tid + j * 256;
            int img = id >> 9, row = (id >> 2) & 127, ch = id & 3;
            cpa16(stg + img * 8192 + swz64(row, ch),
                  &g_Ax[t][mt][img][row][kq * 32 + ch * 8]);
        }
    };
    loadA(0); CP_COMMIT();
    loadA(1); CP_COMMIT();
    loadA(2); CP_COMMIT();

    float acc[2][8][4];
#pragma unroll
    for (int mi = 0; mi < 2; mi++)
#pragma unroll
        for (int nj = 0; nj < 8; nj++)
#pragma unroll
            for (int e = 0; e < 4; e++) acc[mi][nj][e] = 0.0f;

    for (int q = 0; q < QTOT; q++) {
        const int kq = q & 3;
        const int rem = QTOT - 1 - q;
        if (rem >= 2) CP_WAIT2(); else if (rem == 1) CP_WAIT1(); else CP_WAIT0();
        __syncthreads();

        const uint32_t astg = sbase + 32768 + (q % 3) * 16384;
        const uint32_t Ab0 = astg, Ab1 = astg + 8192;
        const uint32_t Bb = sbase + kq * 8192;
#pragma unroll
        for (int ks = 0; ks < 2; ks++) {
            const int ac = 2 * ks + (lane >> 4);
            uint32_t ah[2][4], al[2][4];
#pragma unroll
            for (int fi = 0; fi < 2; fi++) {
                const int row = wm * 32 + fi * 16 + (lane & 15);
                const uint32_t off = swz64(row, ac);
                ldm_x4(ah[fi], Ab0 + off);
                ldm_x4(al[fi], Ab1 + off);
            }
#pragma unroll
            for (int gph = 0; gph < 2; gph++) {
                uint32_t bh2[2][4];
#pragma unroll
                for (int gi = 0; gi < 2; gi++) {
                    const int col = wn * 64 + (gph * 2 + gi) * 16 + (lane & 15);
                    ldm_x4(bh2[gi], Bb + swz64(col, ac));
                }
#pragma unroll
                for (int mi = 0; mi < 2; mi++)
#pragma unroll
                    for (int gi = 0; gi < 2; gi++)
#pragma unroll
                        for (int sub = 0; sub < 2; sub++) {
                            float* d = acc[mi][(gph * 2 + gi) * 2 + sub];
                            mma16816(d, ah[mi], bh2[gi][sub], bh2[gi][sub + 2]);
                            mma16816(d, al[mi], bh2[gi][sub], bh2[gi][sub + 2]);
                        }
            }
        }
        __syncthreads();
        if (q + 3 < QTOT) { loadA(q + 3); CP_COMMIT(); }

        if (kq == 3) {
            const int t = q >> 2;
            float* xgp = g_xg + (((size_t)(dir * T_STEPS + t) * 40 + mt) * 128) * 1024 + nt * 128;
#pragma unroll
            for (int mi = 0; mi < 2; mi++)
#pragma unroll
                for (int nj = 0; nj < 8; nj++) {
                    const int r = wm * 32 + mi * 16 + (lane >> 2);
                    const int c = wn * 64 + nj * 8 + (lane & 3) * 2;
                    const float b0 = bias_sm[c], b1 = bias_sm[c + 1];
                    float2 v0 = { acc[mi][nj][0] + b0, acc[mi][nj][1] + b1 };
                    float2 v1 = { acc[mi][nj][2] + b0, acc[mi][nj][3] + b1 };
                    *(float2*)&xgp[(size_t)r * 1024 + c] = v0;
                    *(float2*)&xgp[(size_t)(r + 8) * 1024 + c] = v1;
#pragma unroll
                    for (int e = 0; e < 4; e++) acc[mi][nj][e] = 0.0f;
                }
        }
    }
}

// ---------------- LSTM step: K=256, 8 chunks of 32, 2-stage, shfl epilogue ----------------
// stage 24KB: A_hi 8K | A_lo 8K | B 8K; 2 stages = 48KB; pack buffer (16.9KB) overlays stage0.
#define ST_SZ    24576
#define SM_TOTAL (2 * ST_SZ)   // 49152

__global__ void __launch_bounds__(256, 2) lstm_step_mma(int s) {
    extern __shared__ __align__(16) unsigned char smem[];
    const uint32_t sbase = smem_u32(smem);
    const int tid = threadIdx.x, wid = tid >> 5, lane = tid & 31;
    const int wm = wid & 3, wn = wid >> 2;
    const int nt = blockIdx.x, mt = blockIdx.y, dir = blockIdx.z;
    const int t = dir ? (T_STEPS - 1 - s) : s;
    const int par = s & 1;

    const __half* Ap = &g_Ah[par][dir][mt][0][0][0];
    const __half* Bp = &g_Bh[dir][nt][0][0];

    auto load_chunk = [&](int ck) {
        const uint32_t stg = sbase + (ck & 1) * ST_SZ;
#pragma unroll
        for (int j = 0; j < 4; j++) {
            int id = tid + j * 256;
            int img = id >> 9, row = (id >> 2) & 127, ch = id & 3;
            cpa16(stg + img * 8192 + swz64(row, ch),
                  &Ap[(size_t)img * 32768 + row * 256 + ck * 32 + ch * 8]);
        }
#pragma unroll
        for (int j = 0; j < 2; j++) {
            int id = tid + j * 256;
            int row = (id >> 2) & 127, ch = id & 3;
            cpa16(stg + 16384 + swz64(row, ch),
                  &Bp[(size_t)row * 256 + ck * 32 + ch * 8]);
        }
    };

    load_chunk(0); CP_COMMIT();
    load_chunk(1); CP_COMMIT();

    // accumulator init from precomputed xg (+bias folded) — overlaps prologue loads
    const float* xgp = g_xg + (((size_t)(dir * T_STEPS + t) * 40 + mt) * 128) * 1024 + nt * 128;
    float acc[2][8][4];
#pragma unroll
    for (int mi = 0; mi < 2; mi++)
#pragma unroll
        for (int nj = 0; nj < 8; nj++) {
            const int r = wm * 32 + mi * 16 + (lane >> 2);
            const int c = wn * 64 + nj * 8 + (lane & 3) * 2;
            float2 v0 = *(const float2*)&xgp[(size_t)r * 1024 + c];
            float2 v1 = *(const float2*)&xgp[(size_t)(r + 8) * 1024 + c];
            acc[mi][nj][0] = v0.x; acc[mi][nj][1] = v0.y;
            acc[mi][nj][2] = v1.x; acc[mi][nj][3] = v1.y;
        }

    // c-state: 16 contiguous floats per thread (fragment layout)
    float* cptr = g_cfrag + (((((size_t)dir * 40 + mt) * 8 + nt) * 8 + wid) * 32 + lane) * 16;
    float creg[16];
    *(float4*)(creg + 0)  = *(const float4*)(cptr + 0);
    *(float4*)(creg + 4)  = *(const float4*)(cptr + 4);
    *(float4*)(creg + 8)  = *(const float4*)(cptr + 8);
    *(float4*)(creg + 12) = *(const float4*)(cptr + 12);

    for (int ck = 0; ck < 8; ck++) {
        if (ck < 7) CP_WAIT1(); else CP_WAIT0();
        __syncthreads();

        const uint32_t stg = sbase + (ck & 1) * ST_SZ;
        const uint32_t Ab0 = stg, Ab1 = stg + 8192;
        const uint32_t Bb = stg + 16384;
#pragma unroll
        for (int ks = 0; ks < 2; ks++) {
            const int ac = 2 * ks + (lane >> 4);
            uint32_t ah[2][4], al[2][4];
#pragma unroll
            for (int fi = 0; fi < 2; fi++) {
                const int row = wm * 32 + fi * 16 + (lane & 15);
                const uint32_t off = swz64(row, ac);
                ldm_x4(ah[fi], Ab0 + off);
                ldm_x4(al[fi], Ab1 + off);
            }
#pragma unroll
            for (int gph = 0; gph < 2; gph++) {
                uint32_t bh2[2][4];
#pragma unroll
                for (int gi = 0; gi < 2; gi++) {
                    const int col = wn * 64 + (gph * 2 + gi) * 16 + (lane & 15);
                    ldm_x4(bh2[gi], Bb + swz64(col, ac));
                }
#pragma unroll
                for (int mi = 0; mi < 2; mi++)
#pragma unroll
                    for (int gi = 0; gi < 2; gi++)
#pragma unroll
                        for (int sub = 0; sub < 2; sub++) {
                            float* d = acc[mi][(gph * 2 + gi) * 2 + sub];
                            mma16816(d, ah[mi], bh2[gi][sub], bh2[gi][sub + 2]);
                            mma16816(d, al[mi], bh2[gi][sub], bh2[gi][sub + 2]);
                        }
            }
        }
        __syncthreads();
        if (ck + 2 < 8) { load_chunk(ck + 2); CP_COMMIT(); }
    }
    __syncthreads();    // stages dead; pack buffer may overlay stage 0

    // ---------------- epilogue: shfl gate assembly + per-thread cell ----------------
    uint32_t* pack = (uint32_t*)smem;   // [128][33] words = 16896 B
    const int rbase = wm * 32 + (lane >> 2) + ((lane & 1) ? 8 : 0);
    const int hb0 = wn * 16 + ((lane >> 1) & 1);
    const bool evenl = (lane & 1) == 0;
#pragma unroll
    for (int mi = 0; mi < 2; mi++) {
#pragma unroll
        for (int nj = 0; nj < 8; nj++) {
            const float v0 = acc[mi][nj][0], v1 = acc[mi][nj][1];
            const float v2 = acc[mi][nj][2], v3 = acc[mi][nj][3];
            const float p0 = __shfl_xor_sync(0xFFFFFFFFu, v0, 1);
            const float p1 = __shfl_xor_sync(0xFFFFFFFFu, v1, 1);
            const float p2 = __shfl_xor_sync(0xFFFFFFFFu, v2, 1);
            const float p3 = __shfl_xor_sync(0xFFFFFFFFu, v3, 1);
            const float gi_ = evenl ? v0 : p2;
            const float gf_ = evenl ? v1 : p3;
            const float gg_ = evenl ? p0 : v2;
            const float go_ = evenl ? p1 : v3;
            const float iv = fsigm(gi_);
            const float fv = fsigm(gf_);
            const float gv = ftanh(gg_);
            const float ov = fsigm(go_);
            const float cn = fv * creg[mi * 8 + nj] + iv * gv;
            creg[mi * 8 + nj] = cn;
            const float hv = ov * ftanh(cn);
            const int row_l = rbase + mi * 16;
            const int hcol = hb0 + nj * 2;
            if (s == T_STEPS - 1)
                g_h[(size_t)dir * NSEQ * HSZ + (size_t)(mt * 128 + row_l) * HSZ
                    + nt * 32 + hcol] = hv;
            uint16_t hbv, lbv; split_h(hv, hbv, lbv);
            pack[row_l * 33 + hcol] = (uint32_t)hbv | ((uint32_t)lbv << 16);
        }
    }
    *(float4*)(cptr + 0)  = *(float4*)(creg + 0);
    *(float4*)(cptr + 4)  = *(float4*)(creg + 4);
    *(float4*)(cptr + 8)  = *(float4*)(creg + 8);
    *(float4*)(cptr + 12) = *(float4*)(creg + 12);
    __syncthreads();

    // pack phase: coalesced 16B global writes of next-step h (hi + lo images)
    {
        const int n_l = tid >> 1;
        const int halfh = tid & 1;
        const int kcol = nt * 32 + halfh * 16;
        uint32_t wv[16];
#pragma unroll
        for (int i = 0; i < 16; i++) wv[i] = pack[n_l * 33 + halfh * 16 + i];
        uint4 u0, u1;
        uint32_t* w;
        w = (uint32_t*)&u0;
#pragma unroll
        for (int q = 0; q < 4; q++)
            w[q] = (wv[q * 2] & 0xFFFFu) | ((wv[q * 2 + 1] & 0xFFFFu) << 16);
        w = (uint32_t*)&u1;
#pragma unroll
        for (int q = 0; q < 4; q++)
            w[q] = (wv[8 + q * 2] & 0xFFFFu) | ((wv[8 + q * 2 + 1] & 0xFFFFu) << 16);
        *(uint4*)&g_Ah[par ^ 1][dir][mt][0][n_l][kcol]     = u0;
        *(uint4*)&g_Ah[par ^ 1][dir][mt][0][n_l][kcol + 8] = u1;
        w = (uint32_t*)&u0;
#pragma unroll
        for (int q = 0; q < 4; q++)
            w[q] = (wv[q * 2] >> 16) | (wv[q * 2 + 1] & 0xFFFF0000u);
        w = (uint32_t*)&u1;
#pragma unroll
        for (int q = 0; q < 4; q++)
            w[q] = (wv[8 + q * 2] >> 16) | (wv[8 + q * 2 + 1] & 0xFFFF0000u);
        *(uint4*)&g_Ah[par ^ 1][dir][mt][1][n_l][kcol]     = u0;
        *(uint4*)&g_Ah[par ^ 1][dir][mt][1][n_l][kcol + 8] = u1;
    }
}

// ---------------- head ----------------
__global__ __launch_bounds__(256) void head_kernel(
    const float* __restrict__ W1, const float* __restrict__ b1,
    const float* __restrict__ W2, const float* __restrict__ b2,
    float* __restrict__ out)
{
    __shared__ float fea[2560];
    __shared__ float zp[4][64];
    __shared__ float zz[64];
    __shared__ float lg[5];

    const int b = blockIdx.x;
    const int tid = threadIdx.x;
    const float* __restrict__ hF = g_h;
    const float* __restrict__ hB = g_h + NSEQ * HSZ;

    for (int i = tid; i < 2560; i += 256) {
        const int slot = i >> 8;
        const int mcol = i & 255;
        const int n = b * 10 + slot;
        const float v = (mcol < 128) ? hF[(size_t)n * HSZ + mcol] : hB[(size_t)n * HSZ + mcol];
        fea[i] = v;
        out[2560 + (size_t)b * 2560 + i] = v;
    }
    __syncthreads();

    const int j = tid & 63;
    const int p = tid >> 6;
    float sum = 0.0f;
    const int k0 = p * 640;
    for (int k = k0; k < k0 + 640; k++) sum += fea[k] * W1[(size_t)j * 2560 + k];
    zp[p][j] = sum;
    __syncthreads();
    if (tid < 64) zz[tid] = zp[0][tid] + zp[1][tid] + zp[2][tid] + zp[3][tid] + b1[tid];
    __syncthreads();

    if (tid < 5) {
        float ss = b2[tid];
        for (int k = 0; k < 64; k++) ss += zz[k] * W2[tid * 64 + k];
        lg[tid] = ss;
    }
    __syncthreads();
    if (tid == 0) {
        float mx = lg[0];
        for (int k = 1; k < 5; k++) mx = fmaxf(mx, lg[k]);
        float e[5], se = 0.0f;
        for (int k = 0; k < 5; k++) { e[k] = expf(lg[k] - mx); se += e[k]; }
        for (int k = 0; k < 5; k++) out[(size_t)b * 5 + k] = e[k] / se;
    }
}

extern "C" void kernel_launch(void* const* d_in, const int* in_sizes, int n_in,
                              void* d_out, int out_size) {
    const float* x     = (const float*)d_in[0];
    const float* h0    = (const float*)d_in[1];
    const float* c0    = (const float*)d_in[2];
    const float* Wih_f = (const float*)d_in[3];
    const float* Whh_f = (const float*)d_in[4];
    const float* bih_f = (const float*)d_in[5];
    const float* bhh_f = (const float*)d_in[6];
    const float* Wih_b = (const float*)d_in[7];
    const float* Whh_b = (const float*)d_in[8];
    const float* bih_b = (const float*)d_in[9];
    const float* bhh_b = (const float*)d_in[10];
    const float* W1    = (const float*)d_in[11];
    const float* b1    = (const float*)d_in[12];
    const float* W2    = (const float*)d_in[13];
    const float* b2    = (const float*)d_in[14];
    float* out = (float*)d_out;

    cudaFuncSetAttribute(xg_gemm, cudaFuncAttributeMaxDynamicSharedMemorySize, XG_SMEM);
    cudaFuncSetAttribute(lstm_step_mma, cudaFuncAttributeMaxDynamicSharedMemorySize, SM_TOTAL);

    // launches: 0 prepack, 1 xg, 2.. steps -> ncu sample lands on a step
    prepack_all<<<(PRE_TOT + 255) / 256, 256>>>(x, h0, c0, Wih_f, Whh_f, bih_f, bhh_f,
                                                Wih_b, Whh_b, bih_b, bhh_b);
    xg_gemm<<<dim3(8, 40, 2), 256, XG_SMEM>>>();

    dim3 grid(8, 40, 2);
    for (int s = 0; s < T_STEPS; s++) {
        lstm_step_mma<<<grid, 256, SM_TOTAL>>>(s);
    }
    head_kernel<<<NBATCH, 256>>>(W1, b1, W2, b2, out);
}

// round 14
// speedup vs baseline: 1.3294x; 1.0137x over previous
#include <cuda_runtime.h>
#include <cuda_fp16.h>
#include <cstdint>
#include <cstring>
#include <math.h>

// ---------------- problem constants ----------------
#define T_STEPS 30
#define ISZ     100
#define HSZ     256
#define NSEQ    5120
#define NBATCH  512

// ---------------- device scratch (allocation-free rule) ----------------
// fp16 2-pass split: activations (A) carry hi+lo images; weights (B) hi only.
__device__ __half g_Ax[T_STEPS][40][2][128][128];   // [t][mt][img][row][k]  x, k pad 100->128
__device__ __half g_Ah[2][2][40][2][128][256];      // [par][dir][mt][img][row][k]
__device__ __half g_Bx[2][8][128][128];             // [dir][nt8][c'][k]  Wih, gate-interleaved, hi only
__device__ __half g_Bh[2][8][128][256];             // [dir][nt8][c'][k]  Whh, hi only
__device__ float g_bias[2][1024];                   // [dir][c'=h*4+g]
// c-state in MMA-fragment layout: [dir][mt][nt][wid][lane][mi*8+nj] (16 floats per thread)
__device__ float g_cfrag[(size_t)2 * 40 * 8 * 8 * 32 * 16];
__device__ float g_h[2 * NSEQ * HSZ];               // finals only (s==29), standard layout
__device__ float g_xg[(size_t)2 * T_STEPS * 40 * 128 * 1024]; // [dir][t][mt][row][c']

// ---------------- helpers ----------------
__device__ __forceinline__ uint32_t smem_u32(const void* p) {
    uint32_t a;
    asm("{ .reg .u64 t; cvta.to.shared.u64 t, %1; cvt.u32.u64 %0, t; }" : "=r"(a) : "l"(p));
    return a;
}
__device__ __forceinline__ void cpa16(uint32_t dst, const void* src) {
    asm volatile("cp.async.cg.shared.global [%0], [%1], 16;" :: "r"(dst), "l"(src));
}
#define CP_COMMIT() asm volatile("cp.async.commit_group;" ::: "memory")
#define CP_WAIT1()  asm volatile("cp.async.wait_group 1;" ::: "memory")
#define CP_WAIT0()  asm volatile("cp.async.wait_group 0;" ::: "memory")

__device__ __forceinline__ void ldm_x4(uint32_t* r, uint32_t addr) {
    asm volatile("ldmatrix.sync.aligned.m8n8.x4.shared.b16 {%0,%1,%2,%3}, [%4];"
                 : "=r"(r[0]), "=r"(r[1]), "=r"(r[2]), "=r"(r[3]) : "r"(addr));
}
__device__ __forceinline__ void mma16816(float* d, const uint32_t* a, uint32_t b0, uint32_t b1) {
    asm volatile(
        "mma.sync.aligned.m16n8k16.row.col.f32.f16.f16.f32 "
        "{%0,%1,%2,%3}, {%4,%5,%6,%7}, {%8,%9}, {%0,%1,%2,%3};"
        : "+f"(d[0]), "+f"(d[1]), "+f"(d[2]), "+f"(d[3])
        : "r"(a[0]), "r"(a[1]), "r"(a[2]), "r"(a[3]), "r"(b0), "r"(b1));
}
// 128B-row swizzle (8 x 16B chunks per row)
__device__ __forceinline__ uint32_t swz128(int row, int ch) {
    return (uint32_t)(row * 128 + ((ch ^ (row & 7)) << 4));
}
__device__ __forceinline__ float fsigm(float x) {
    float e;
    asm("ex2.approx.f32 %0, %1;" : "=f"(e) : "f"(x * -1.4426950408889634f));
    float r;
    asm("rcp.approx.f32 %0, %1;" : "=f"(r) : "f"(1.0f + e));
    return r;
}
__device__ __forceinline__ float ftanh(float x) { return fmaf(2.0f, fsigm(2.0f * x), -1.0f); }
__device__ __forceinline__ void split_h(float v, uint16_t& hi_b, uint16_t& lo_b) {
    __half h = __float2half_rn(v);
    float hf = __half2float(h);
    memcpy(&hi_b, &h, 2);
    __half l = __float2half_rn(v - hf);
    memcpy(&lo_b, &l, 2);
}

// ---------------- merged prepack (ONE launch) ----------------
#define SEG_BIAS 2048
#define SEG_W    (2 * 8 * 128 * 384)
#define SEG_X    (T_STEPS * NSEQ * 128)
#define SEG_HC   (2 * NSEQ * HSZ)
#define PRE_TOT  (SEG_BIAS + SEG_W + SEG_X + SEG_HC)

__global__ void prepack_all(const float* __restrict__ x,
                            const float* __restrict__ h0, const float* __restrict__ c0,
                            const float* __restrict__ Wih_f, const float* __restrict__ Whh_f,
                            const float* __restrict__ bih_f, const float* __restrict__ bhh_f,
                            const float* __restrict__ Wih_b, const float* __restrict__ Whh_b,
                            const float* __restrict__ bih_b, const float* __restrict__ bhh_b) {
    int idx = blockIdx.x * blockDim.x + threadIdx.x;
    if (idx < SEG_BIAS) {
        int c = idx & 1023, dir = idx >> 10;
        int h = c >> 2, g = c & 3;
        int row = g * HSZ + h;
        g_bias[dir][c] = dir ? (bih_b[row] + bhh_b[row]) : (bih_f[row] + bhh_f[row]);
        return;
    }
    idx -= SEG_BIAS;
    if (idx < SEG_W) {
        int k = idx % 384;
        int rest = idx / 384;
        int c = rest & 127;
        rest >>= 7;
        int nt = rest & 7;
        int dir = rest >> 3;
        const float* Wih = dir ? Wih_b : Wih_f;
        const float* Whh = dir ? Whh_b : Whh_f;
        int hg = nt * 32 + (c >> 2);
        int g = c & 3;
        int row = g * HSZ + hg;
        if (k < 128) {
            float v = (k < ISZ) ? Wih[(size_t)row * ISZ + k] : 0.0f;
            g_Bx[dir][nt][c][k] = __float2half_rn(v);
        } else {
            float v = Whh[(size_t)row * HSZ + (k - 128)];
            g_Bh[dir][nt][c][k - 128] = __float2half_rn(v);
        }
        return;
    }
    idx -= SEG_W;
    if (idx < SEG_X) {
        int k = idx & 127;
        int n = (idx >> 7) % NSEQ;
        int t = idx / (NSEQ * 128);
        float v = (k < ISZ) ? x[((size_t)n * T_STEPS + t) * ISZ + k] : 0.0f;
        uint16_t hb, lb; split_h(v, hb, lb);
        int mt = n >> 7, m = n & 127;
        memcpy(&g_Ax[t][mt][0][m][k], &hb, 2);
        memcpy(&g_Ax[t][mt][1][m][k], &lb, 2);
        return;
    }
    idx -= SEG_X;
    if (idx < SEG_HC) {
        int k = idx & 255;
        int n = (idx >> 8) % NSEQ;
        int d = idx / (NSEQ * HSZ);
        // c0 -> fragment layout
        {
            int mt = n >> 7, row_l = n & 127;
            int nt = k >> 5, h_l = k & 31;
            int wm = row_l >> 5, mi = (row_l >> 4) & 1, rsub = row_l & 15;
            int wn = h_l >> 4, nj = (h_l & 15) >> 1, hbit = h_l & 1;
            int lane = ((rsub & 7) << 2) | (hbit << 1) | (rsub >> 3);
            int wid = wm | (wn << 2);
            size_t fidx = (((((size_t)d * 40 + mt) * 8 + nt) * 8 + wid) * 32 + lane) * 16
                          + mi * 8 + nj;
            g_cfrag[fidx] = c0[idx];
        }
        // h0 -> packed hi/lo images (parity 0)
        float v = h0[idx];
        uint16_t hb, lb; split_h(v, hb, lb);
        int mt = n >> 7, m = n & 127;
        memcpy(&g_Ah[0][d][mt][0][m][k], &hb, 2);
        memcpy(&g_Ah[0][d][mt][1][m][k], &lb, 2);
    }
}

// ---------------- xg GEMM: N=128 tiles, B-resident 32KB, k=64 chunks (60 iters) --------
// smem: B 32KB (2 blocks kh*16384 of [c128][k64]) @0 | A stages 2x32KB @32768 | bias @98304
#define XG_SMEM  (32768 + 2 * 32768 + 512)   // 98816
#define QTOT     (T_STEPS * 2)               // 60 k-half chunks

__global__ void __launch_bounds__(256, 2) xg_gemm(void) {
    extern __shared__ __align__(16) unsigned char smem[];
    const uint32_t sbase = smem_u32(smem);
    const int tid = threadIdx.x, wid = tid >> 5, lane = tid & 31;
    const int wm = wid & 3, wn = wid >> 2;   // warp tile: 32 rows x 64 cols
    const int nt = blockIdx.x;               // 8 tiles of 128 cols
    const int mt = blockIdx.y, dir = blockIdx.z;

    float* bias_sm = (float*)(smem + 98304);
    if (tid < 128) bias_sm[tid] = g_bias[dir][nt * 128 + tid];

    // load resident B (32KB): 2 blocks (kh) of [c 128][k 64], hi only
    {
#pragma unroll
        for (int j = 0; j < 8; j++) {
            int id = tid + j * 256;
            int kh = id >> 10, row = (id >> 3) & 127, ch = id & 7;
            cpa16(sbase + kh * 16384 + swz128(row, ch),
                  &g_Bx[dir][nt][row][kh * 64 + ch * 8]);
        }
    }
    CP_COMMIT();

    auto loadA = [&](int q) {   // q = t*2 + kh
        const int t = q >> 1, kh = q & 1;
        const uint32_t stg = sbase + 32768 + (q & 1) * 32768;
#pragma unroll
        for (int j = 0; j < 8; j++) {
            int id = tid + j * 256;
            int img = id >> 10, row = (id >> 3) & 127, ch = id & 7;
            cpa16(stg + img * 16384 + swz128(row, ch),
                  &g_Ax[t][mt][img][row][kh * 64 + ch * 8]);
        }
    };
    loadA(0); CP_COMMIT();
    loadA(1); CP_COMMIT();

    float acc[2][8][4];
#pragma unroll
    for (int mi = 0; mi < 2; mi++)
#pragma unroll
        for (int nj = 0; nj < 8; nj++)
#pragma unroll
            for (int e = 0; e < 4; e++) acc[mi][nj][e] = 0.0f;

    for (int q = 0; q < QTOT; q++) {
        const int kh = q & 1;
        if (q < QTOT - 1) CP_WAIT1(); else CP_WAIT0();
        __syncthreads();

        const uint32_t astg = sbase + 32768 + (q & 1) * 32768;
        const uint32_t Ab0 = astg, Ab1 = astg + 16384;
        const uint32_t Bb = sbase + kh * 16384;
#pragma unroll
        for (int ks = 0; ks < 4; ks++) {
            const int ac = 2 * ks + (lane >> 4);
            uint32_t ah[2][4], al[2][4];
#pragma unroll
            for (int fi = 0; fi < 2; fi++) {
                const int row = wm * 32 + fi * 16 + (lane & 15);
                const uint32_t off = swz128(row, ac);
                ldm_x4(ah[fi], Ab0 + off);
                ldm_x4(al[fi], Ab1 + off);
            }
#pragma unroll
            for (int gph = 0; gph < 2; gph++) {
                uint32_t bh2[2][4];
#pragma unroll
                for (int gi = 0; gi < 2; gi++) {
                    const int col = wn * 64 + (gph * 2 + gi) * 16 + (lane & 15);
                    ldm_x4(bh2[gi], Bb + swz128(col, ac));
                }
#pragma unroll
                for (int mi = 0; mi < 2; mi++)
#pragma unroll
                    for (int gi = 0; gi < 2; gi++)
#pragma unroll
                        for (int sub = 0; sub < 2; sub++) {
                            float* d = acc[mi][(gph * 2 + gi) * 2 + sub];
                            mma16816(d, ah[mi], bh2[gi][sub], bh2[gi][sub + 2]);
                            mma16816(d, al[mi], bh2[gi][sub], bh2[gi][sub + 2]);
                        }
            }
        }
        __syncthreads();
        if (q + 2 < QTOT) { loadA(q + 2); CP_COMMIT(); }

        if (kh == 1) {
            const int t = q >> 1;
            float* xgp = g_xg + (((size_t)(dir * T_STEPS + t) * 40 + mt) * 128) * 1024 + nt * 128;
#pragma unroll
            for (int mi = 0; mi < 2; mi++)
#pragma unroll
                for (int nj = 0; nj < 8; nj++) {
                    const int r = wm * 32 + mi * 16 + (lane >> 2);
                    const int c = wn * 64 + nj * 8 + (lane & 3) * 2;
                    const float b0 = bias_sm[c], b1 = bias_sm[c + 1];
                    float2 v0 = { acc[mi][nj][0] + b0, acc[mi][nj][1] + b1 };
                    float2 v1 = { acc[mi][nj][2] + b0, acc[mi][nj][3] + b1 };
                    *(float2*)&xgp[(size_t)r * 1024 + c] = v0;
                    *(float2*)&xgp[(size_t)(r + 8) * 1024 + c] = v1;
#pragma unroll
                    for (int e = 0; e < 4; e++) acc[mi][nj][e] = 0.0f;
                }
        }
    }
}

// ---------------- LSTM step: K=256 in 4 chunks of 64, 2-stage, shfl epilogue ----------
// stage 48KB: A_hi 16K | A_lo 16K | B 16K; 2 stages = 96KB; pack (16.9KB) overlays stage0.
#define ST_SZ    49152
#define SM_TOTAL (2 * ST_SZ)   // 98304

__global__ void __launch_bounds__(256, 2) lstm_step_mma(int s) {
    extern __shared__ __align__(16) unsigned char smem[];
    const uint32_t sbase = smem_u32(smem);
    const int tid = threadIdx.x, wid = tid >> 5, lane = tid & 31;
    const int wm = wid & 3, wn = wid >> 2;
    const int nt = blockIdx.x, mt = blockIdx.y, dir = blockIdx.z;
    const int t = dir ? (T_STEPS - 1 - s) : s;
    const int par = s & 1;

    const __half* Ap = &g_Ah[par][dir][mt][0][0][0];
    const __half* Bp = &g_Bh[dir][nt][0][0];

    auto load_chunk = [&](int ck) {
        const uint32_t stg = sbase + (ck & 1) * ST_SZ;
#pragma unroll
        for (int j = 0; j < 8; j++) {
            int id = tid + j * 256;
            int img = id >> 10, row = (id >> 3) & 127, ch = id & 7;
            cpa16(stg + img * 16384 + swz128(row, ch),
                  &Ap[(size_t)img * 32768 + row * 256 + ck * 64 + ch * 8]);
        }
#pragma unroll
        for (int j = 0; j < 4; j++) {
            int id = tid + j * 256;
            int row = (id >> 3) & 127, ch = id & 7;
            cpa16(stg + 32768 + swz128(row, ch),
                  &Bp[(size_t)row * 256 + ck * 64 + ch * 8]);
        }
    };

    load_chunk(0); CP_COMMIT();
    load_chunk(1); CP_COMMIT();

    // accumulator init from precomputed xg (+bias folded) — overlaps prologue loads
    const float* xgp = g_xg + (((size_t)(dir * T_STEPS + t) * 40 + mt) * 128) * 1024 + nt * 128;
    float acc[2][8][4];
#pragma unroll
    for (int mi = 0; mi < 2; mi++)
#pragma unroll
        for (int nj = 0; nj < 8; nj++) {
            const int r = wm * 32 + mi * 16 + (lane >> 2);
            const int c = wn * 64 + nj * 8 + (lane & 3) * 2;
            float2 v0 = *(const float2*)&xgp[(size_t)r * 1024 + c];
            float2 v1 = *(const float2*)&xgp[(size_t)(r + 8) * 1024 + c];
            acc[mi][nj][0] = v0.x; acc[mi][nj][1] = v0.y;
            acc[mi][nj][2] = v1.x; acc[mi][nj][3] = v1.y;
        }

    // c-state: 16 contiguous floats per thread (fragment layout)
    float* cptr = g_cfrag + (((((size_t)dir * 40 + mt) * 8 + nt) * 8 + wid) * 32 + lane) * 16;
    float creg[16];
    *(float4*)(creg + 0)  = *(const float4*)(cptr + 0);
    *(float4*)(creg + 4)  = *(const float4*)(cptr + 4);
    *(float4*)(creg + 8)  = *(const float4*)(cptr + 8);
    *(float4*)(creg + 12) = *(const float4*)(cptr + 12);

    for (int ck = 0; ck < 4; ck++) {
        if (ck < 3) CP_WAIT1(); else CP_WAIT0();
        __syncthreads();

        const uint32_t stg = sbase + (ck & 1) * ST_SZ;
        const uint32_t Ab0 = stg, Ab1 = stg + 16384;
        const uint32_t Bb = stg + 32768;
#pragma unroll
        for (int ks = 0; ks < 4; ks++) {
            const int ac = 2 * ks + (lane >> 4);
            uint32_t ah[2][4], al[2][4];
#pragma unroll
            for (int fi = 0; fi < 2; fi++) {
                const int row = wm * 32 + fi * 16 + (lane & 15);
                const uint32_t off = swz128(row, ac);
                ldm_x4(ah[fi], Ab0 + off);
                ldm_x4(al[fi], Ab1 + off);
            }
#pragma unroll
            for (int gph = 0; gph < 2; gph++) {
                uint32_t bh2[2][4];
#pragma unroll
                for (int gi = 0; gi < 2; gi++) {
                    const int col = wn * 64 + (gph * 2 + gi) * 16 + (lane & 15);
                    ldm_x4(bh2[gi], Bb + swz128(col, ac));
                }
#pragma unroll
                for (int mi = 0; mi < 2; mi++)
#pragma unroll
                    for (int gi = 0; gi < 2; gi++)
#pragma unroll
                        for (int sub = 0; sub < 2; sub++) {
                            float* d = acc[mi][(gph * 2 + gi) * 2 + sub];
                            mma16816(d, ah[mi], bh2[gi][sub], bh2[gi][sub + 2]);
                            mma16816(d, al[mi], bh2[gi][sub], bh2[gi][sub + 2]);
                        }
            }
        }
        __syncthreads();
        if (ck + 2 < 4) { load_chunk(ck + 2); CP_COMMIT(); }
    }

    // ---------------- epilogue: shfl gate assembly + per-thread cell ----------------
    uint32_t* pack = (uint32_t*)smem;   // [128][33] words = 16896 B (overlays stage 0)
    const int rbase = wm * 32 + (lane >> 2) + ((lane & 1) ? 8 : 0);
    const int hb0 = wn * 16 + ((lane >> 1) & 1);
    const bool evenl = (lane & 1) == 0;
#pragma unroll
    for (int mi = 0; mi < 2; mi++) {
#pragma unroll
        for (int nj = 0; nj < 8; nj++) {
            const float v0 = acc[mi][nj][0], v1 = acc[mi][nj][1];
            const float v2 = acc[mi][nj][2], v3 = acc[mi][nj][3];
            const float p0 = __shfl_xor_sync(0xFFFFFFFFu, v0, 1);
            const float p1 = __shfl_xor_sync(0xFFFFFFFFu, v1, 1);
            const float p2 = __shfl_xor_sync(0xFFFFFFFFu, v2, 1);
            const float p3 = __shfl_xor_sync(0xFFFFFFFFu, v3, 1);
            const float gi_ = evenl ? v0 : p2;
            const float gf_ = evenl ? v1 : p3;
            const float gg_ = evenl ? p0 : v2;
            const float go_ = evenl ? p1 : v3;
            const float iv = fsigm(gi_);
            const float fv = fsigm(gf_);
            const float gv = ftanh(gg_);
            const float ov = fsigm(go_);
            const float cn = fv * creg[mi * 8 + nj] + iv * gv;
            creg[mi * 8 + nj] = cn;
            const float hv = ov * ftanh(cn);
            const int row_l = rbase + mi * 16;
            const int hcol = hb0 + nj * 2;
            if (s == T_STEPS - 1)
                g_h[(size_t)dir * NSEQ * HSZ + (size_t)(mt * 128 + row_l) * HSZ
                    + nt * 32 + hcol] = hv;
            uint16_t hbv, lbv; split_h(hv, hbv, lbv);
            pack[row_l * 33 + hcol] = (uint32_t)hbv | ((uint32_t)lbv << 16);
        }
    }
    *(float4*)(cptr + 0)  = *(float4*)(creg + 0);
    *(float4*)(cptr + 4)  = *(float4*)(creg + 4);
    *(float4*)(cptr + 8)  = *(float4*)(creg + 8);
    *(float4*)(cptr + 12) = *(float4*)(creg + 12);
    __syncthreads();

    // pack phase: coalesced 16B global writes of next-step h (hi + lo images)
    {
        const int n_l = tid >> 1;
        const int halfh = tid & 1;
        const int kcol = nt * 32 + halfh * 16;
        uint32_t wv[16];
#pragma unroll
        for (int i = 0; i < 16; i++) wv[i] = pack[n_l * 33 + halfh * 16 + i];
        uint4 u0, u1;
        uint32_t* w;
        w = (uint32_t*)&u0;
#pragma unroll
        for (int q = 0; q < 4; q++)
            w[q] = (wv[q * 2] & 0xFFFFu) | ((wv[q * 2 + 1] & 0xFFFFu) << 16);
        w = (uint32_t*)&u1;
#pragma unroll
        for (int q = 0; q < 4; q++)
            w[q] = (wv[8 + q * 2] & 0xFFFFu) | ((wv[8 + q * 2 + 1] & 0xFFFFu) << 16);
        *(uint4*)&g_Ah[par ^ 1][dir][mt][0][n_l][kcol]     = u0;
        *(uint4*)&g_Ah[par ^ 1][dir][mt][0][n_l][kcol + 8] = u1;
        w = (uint32_t*)&u0;
#pragma unroll
        for (int q = 0; q < 4; q++)
            w[q] = (wv[q * 2] >> 16) | (wv[q * 2 + 1] & 0xFFFF0000u);
        w = (uint32_t*)&u1;
#pragma unroll
        for (int q = 0; q < 4; q++)
            w[q] = (wv[8 + q * 2] >> 16) | (wv[8 + q * 2 + 1] & 0xFFFF0000u);
        *(uint4*)&g_Ah[par ^ 1][dir][mt][1][n_l][kcol]     = u0;
        *(uint4*)&g_Ah[par ^ 1][dir][mt][1][n_l][kcol + 8] = u1;
    }
}

// ---------------- head ----------------
__global__ __launch_bounds__(256) void head_kernel(
    const float* __restrict__ W1, const float* __restrict__ b1,
    const float* __restrict__ W2, const float* __restrict__ b2,
    float* __restrict__ out)
{
    __shared__ float fea[2560];
    __shared__ float zp[4][64];
    __shared__ float zz[64];
    __shared__ float lg[5];

    const int b = blockIdx.x;
    const int tid = threadIdx.x;
    const float* __restrict__ hF = g_h;
    const float* __restrict__ hB = g_h + NSEQ * HSZ;

    for (int i = tid; i < 2560; i += 256) {
        const int slot = i >> 8;
        const int mcol = i & 255;
        const int n = b * 10 + slot;
        const float v = (mcol < 128) ? hF[(size_t)n * HSZ + mcol] : hB[(size_t)n * HSZ + mcol];
        fea[i] = v;
        out[2560 + (size_t)b * 2560 + i] = v;
    }
    __syncthreads();

    const int j = tid & 63;
    const int p = tid >> 6;
    float sum = 0.0f;
    const int k0 = p * 640;
    for (int k = k0; k < k0 + 640; k++) sum += fea[k] * W1[(size_t)j * 2560 + k];
    zp[p][j] = sum;
    __syncthreads();
    if (tid < 64) zz[tid] = zp[0][tid] + zp[1][tid] + zp[2][tid] + zp[3][tid] + b1[tid];
    __syncthreads();

    if (tid < 5) {
        float ss = b2[tid];
        for (int k = 0; k < 64; k++) ss += zz[k] * W2[tid * 64 + k];
        lg[tid] = ss;
    }
    __syncthreads();
    if (tid == 0) {
        float mx = lg[0];
        for (int k = 1; k < 5; k++) mx = fmaxf(mx, lg[k]);
        float e[5], se = 0.0f;
        for (int k = 0; k < 5; k++) { e[k] = expf(lg[k] - mx); se += e[k]; }
        for (int k = 0; k < 5; k++) out[(size_t)b * 5 + k] = e[k] / se;
    }
}

extern "C" void kernel_launch(void* const* d_in, const int* in_sizes, int n_in,
                              void* d_out, int out_size) {
    const float* x     = (const float*)d_in[0];
    const float* h0    = (const float*)d_in[1];
    const float* c0    = (const float*)d_in[2];
    const float* Wih_f = (const float*)d_in[3];
    const float* Whh_f = (const float*)d_in[4];
    const float* bih_f = (const float*)d_in[5];
    const float* bhh_f = (const float*)d_in[6];
    const float* Wih_b = (const float*)d_in[7];
    const float* Whh_b = (const float*)d_in[8];
    const float* bih_b = (const float*)d_in[9];
    const float* bhh_b = (const float*)d_in[10];
    const float* W1    = (const float*)d_in[11];
    const float* b1    = (const float*)d_in[12];
    const float* W2    = (const float*)d_in[13];
    const float* b2    = (const float*)d_in[14];
    float* out = (float*)d_out;

    cudaFuncSetAttribute(xg_gemm, cudaFuncAttributeMaxDynamicSharedMemorySize, XG_SMEM);
    cudaFuncSetAttribute(lstm_step_mma, cudaFuncAttributeMaxDynamicSharedMemorySize, SM_TOTAL);

    // launches: 0 prepack, 1 xg, 2.. steps -> ncu sample lands on a step
    prepack_all<<<(PRE_TOT + 255) / 256, 256>>>(x, h0, c0, Wih_f, Whh_f, bih_f, bhh_f,
                                                Wih_b, Whh_b, bih_b, bhh_b);
    xg_gemm<<<dim3(8, 40, 2), 256, XG_SMEM>>>();

    dim3 grid(8, 40, 2);
    for (int s = 0; s < T_STEPS; s++) {
        lstm_step_mma<<<grid, 256, SM_TOTAL>>>(s);
    }
    head_kernel<<<NBATCH, 256>>>(W1, b1, W2, b2, out);
}

// round 15
// speedup vs baseline: 1.4613x; 1.0992x over previous
#include <cuda_runtime.h>
#include <cuda_fp16.h>
#include <cstdint>
#include <cstring>
#include <math.h>

// ---------------- problem constants ----------------
#define T_STEPS 30
#define ISZ     100
#define HSZ     256
#define NSEQ    5120
#define NBATCH  512

// ---------------- device scratch (allocation-free rule) ----------------
// x: single fp16 image (xg GEMM is 1-pass); h: hi+lo images (step GEMM stays 2-pass).
__device__ __half g_Ax[T_STEPS][40][128][128];      // [t][mt][row][k]  x hi, k pad 100->128
__device__ __half g_Ah[2][2][40][2][128][256];      // [par][dir][mt][img][row][k]
__device__ __half g_Bx[2][8][128][128];             // [dir][nt8][c'][k]  Wih, gate-interleaved, hi
__device__ __half g_Bh[2][8][128][256];             // [dir][nt8][c'][k]  Whh, hi
__device__ float g_bias[2][1024];                   // [dir][c'=h*4+g]
// c-state in MMA-fragment layout: [dir][mt][nt][wid][lane][mi*8+nj] (16 floats per thread)
__device__ float g_cfrag[(size_t)2 * 40 * 8 * 8 * 32 * 16];
__device__ float g_h[2 * NSEQ * HSZ];               // finals only (s==29), standard layout
__device__ float g_xg[(size_t)2 * T_STEPS * 40 * 128 * 1024]; // [dir][t][mt][row][c']

// ---------------- helpers ----------------
__device__ __forceinline__ uint32_t smem_u32(const void* p) {
    uint32_t a;
    asm("{ .reg .u64 t; cvta.to.shared.u64 t, %1; cvt.u32.u64 %0, t; }" : "=r"(a) : "l"(p));
    return a;
}
__device__ __forceinline__ void cpa16(uint32_t dst, const void* src) {
    asm volatile("cp.async.cg.shared.global [%0], [%1], 16;" :: "r"(dst), "l"(src));
}
#define CP_COMMIT() asm volatile("cp.async.commit_group;" ::: "memory")
#define CP_WAIT1()  asm volatile("cp.async.wait_group 1;" ::: "memory")
#define CP_WAIT0()  asm volatile("cp.async.wait_group 0;" ::: "memory")

__device__ __forceinline__ void ldm_x4(uint32_t* r, uint32_t addr) {
    asm volatile("ldmatrix.sync.aligned.m8n8.x4.shared.b16 {%0,%1,%2,%3}, [%4];"
                 : "=r"(r[0]), "=r"(r[1]), "=r"(r[2]), "=r"(r[3]) : "r"(addr));
}
__device__ __forceinline__ void mma16816(float* d, const uint32_t* a, uint32_t b0, uint32_t b1) {
    asm volatile(
        "mma.sync.aligned.m16n8k16.row.col.f32.f16.f16.f32 "
        "{%0,%1,%2,%3}, {%4,%5,%6,%7}, {%8,%9}, {%0,%1,%2,%3};"
        : "+f"(d[0]), "+f"(d[1]), "+f"(d[2]), "+f"(d[3])
        : "r"(a[0]), "r"(a[1]), "r"(a[2]), "r"(a[3]), "r"(b0), "r"(b1));
}
// 128B-row swizzle (8 x 16B chunks per row)
__device__ __forceinline__ uint32_t swz128(int row, int ch) {
    return (uint32_t)(row * 128 + ((ch ^ (row & 7)) << 4));
}
__device__ __forceinline__ float fsigm(float x) {
    float e;
    asm("ex2.approx.f32 %0, %1;" : "=f"(e) : "f"(x * -1.4426950408889634f));
    float r;
    asm("rcp.approx.f32 %0, %1;" : "=f"(r) : "f"(1.0f + e));
    return r;
}
__device__ __forceinline__ float ftanh(float x) { return fmaf(2.0f, fsigm(2.0f * x), -1.0f); }
__device__ __forceinline__ void split_h(float v, uint16_t& hi_b, uint16_t& lo_b) {
    __half h = __float2half_rn(v);
    float hf = __half2float(h);
    memcpy(&hi_b, &h, 2);
    __half l = __float2half_rn(v - hf);
    memcpy(&lo_b, &l, 2);
}

// ---------------- merged prepack (ONE launch) ----------------
#define SEG_BIAS 2048
#define SEG_W    (2 * 8 * 128 * 384)
#define SEG_X    (T_STEPS * NSEQ * 128)
#define SEG_HC   (2 * NSEQ * HSZ)
#define PRE_TOT  (SEG_BIAS + SEG_W + SEG_X + SEG_HC)

__global__ void prepack_all(const float* __restrict__ x,
                            const float* __restrict__ h0, const float* __restrict__ c0,
                            const float* __restrict__ Wih_f, const float* __restrict__ Whh_f,
                            const float* __restrict__ bih_f, const float* __restrict__ bhh_f,
                            const float* __restrict__ Wih_b, const float* __restrict__ Whh_b,
                            const float* __restrict__ bih_b, const float* __restrict__ bhh_b) {
    int idx = blockIdx.x * blockDim.x + threadIdx.x;
    if (idx < SEG_BIAS) {
        int c = idx & 1023, dir = idx >> 10;
        int h = c >> 2, g = c & 3;
        int row = g * HSZ + h;
        g_bias[dir][c] = dir ? (bih_b[row] + bhh_b[row]) : (bih_f[row] + bhh_f[row]);
        return;
    }
    idx -= SEG_BIAS;
    if (idx < SEG_W) {
        int k = idx % 384;
        int rest = idx / 384;
        int c = rest & 127;
        rest >>= 7;
        int nt = rest & 7;
        int dir = rest >> 3;
        const float* Wih = dir ? Wih_b : Wih_f;
        const float* Whh = dir ? Whh_b : Whh_f;
        int hg = nt * 32 + (c >> 2);
        int g = c & 3;
        int row = g * HSZ + hg;
        if (k < 128) {
            float v = (k < ISZ) ? Wih[(size_t)row * ISZ + k] : 0.0f;
            g_Bx[dir][nt][c][k] = __float2half_rn(v);
        } else {
            float v = Whh[(size_t)row * HSZ + (k - 128)];
            g_Bh[dir][nt][c][k - 128] = __float2half_rn(v);
        }
        return;
    }
    idx -= SEG_W;
    if (idx < SEG_X) {
        int k = idx & 127;
        int n = (idx >> 7) % NSEQ;
        int t = idx / (NSEQ * 128);
        float v = (k < ISZ) ? x[((size_t)n * T_STEPS + t) * ISZ + k] : 0.0f;
        int mt = n >> 7, m = n & 127;
        g_Ax[t][mt][m][k] = __float2half_rn(v);   // hi only (xg is 1-pass)
        return;
    }
    idx -= SEG_X;
    if (idx < SEG_HC) {
        int k = idx & 255;
        int n = (idx >> 8) % NSEQ;
        int d = idx / (NSEQ * HSZ);
        // c0 -> fragment layout
        {
            int mt = n >> 7, row_l = n & 127;
            int nt = k >> 5, h_l = k & 31;
            int wm = row_l >> 5, mi = (row_l >> 4) & 1, rsub = row_l & 15;
            int wn = h_l >> 4, nj = (h_l & 15) >> 1, hbit = h_l & 1;
            int lane = ((rsub & 7) << 2) | (hbit << 1) | (rsub >> 3);
            int wid = wm | (wn << 2);
            size_t fidx = (((((size_t)d * 40 + mt) * 8 + nt) * 8 + wid) * 32 + lane) * 16
                          + mi * 8 + nj;
            g_cfrag[fidx] = c0[idx];
        }
        // h0 -> packed hi/lo images (parity 0)
        float v = h0[idx];
        uint16_t hb, lb; split_h(v, hb, lb);
        int mt = n >> 7, m = n & 127;
        memcpy(&g_Ah[0][d][mt][0][m][k], &hb, 2);
        memcpy(&g_Ah[0][d][mt][1][m][k], &lb, 2);
    }
}

// ---------------- xg GEMM: 1-pass fp16, N=128 tiles, one t per iteration (30 iters) ----
// smem: B 32KB (2 blocks kh*16384 of [c128][k64]) @0 | A stages 2x32KB @32768 | bias @98304
// A stage layout: 2 blocks kh*16384 of [row128][k64].
#define XG_SMEM  (32768 + 2 * 32768 + 512)   // 98816

__global__ void __launch_bounds__(256, 2) xg_gemm(void) {
    extern __shared__ __align__(16) unsigned char smem[];
    const uint32_t sbase = smem_u32(smem);
    const int tid = threadIdx.x, wid = tid >> 5, lane = tid & 31;
    const int wm = wid & 3, wn = wid >> 2;   // warp tile: 32 rows x 64 cols
    const int nt = blockIdx.x;               // 8 tiles of 128 cols
    const int mt = blockIdx.y, dir = blockIdx.z;

    float* bias_sm = (float*)(smem + 98304);
    if (tid < 128) bias_sm[tid] = g_bias[dir][nt * 128 + tid];

    // load resident B (32KB): 2 blocks (kh) of [c 128][k 64], hi only
    {
#pragma unroll
        for (int j = 0; j < 8; j++) {
            int id = tid + j * 256;
            int kh = id >> 10, row = (id >> 3) & 127, ch = id & 7;
            cpa16(sbase + kh * 16384 + swz128(row, ch),
                  &g_Bx[dir][nt][row][kh * 64 + ch * 8]);
        }
    }
    CP_COMMIT();

    auto loadA = [&](int t) {
        const uint32_t stg = sbase + 32768 + (t & 1) * 32768;
#pragma unroll
        for (int j = 0; j < 8; j++) {
            int id = tid + j * 256;
            int kh = id >> 10, row = (id >> 3) & 127, ch = id & 7;
            cpa16(stg + kh * 16384 + swz128(row, ch),
                  &g_Ax[t][mt][row][kh * 64 + ch * 8]);
        }
    };
    loadA(0); CP_COMMIT();
    loadA(1); CP_COMMIT();

    for (int t = 0; t < T_STEPS; t++) {
        if (t < T_STEPS - 1) CP_WAIT1(); else CP_WAIT0();
        __syncthreads();

        float acc[2][8][4];
#pragma unroll
        for (int mi = 0; mi < 2; mi++)
#pragma unroll
            for (int nj = 0; nj < 8; nj++)
#pragma unroll
                for (int e = 0; e < 4; e++) acc[mi][nj][e] = 0.0f;

        const uint32_t astg = sbase + 32768 + (t & 1) * 32768;
#pragma unroll
        for (int kh = 0; kh < 2; kh++) {
            const uint32_t Ab = astg + kh * 16384;
            const uint32_t Bb = sbase + kh * 16384;
#pragma unroll
            for (int ks = 0; ks < 4; ks++) {
                const int ac = 2 * ks + (lane >> 4);
                uint32_t ah[2][4];
#pragma unroll
                for (int fi = 0; fi < 2; fi++) {
                    const int row = wm * 32 + fi * 16 + (lane & 15);
                    ldm_x4(ah[fi], Ab + swz128(row, ac));
                }
#pragma unroll
                for (int gph = 0; gph < 2; gph++) {
                    uint32_t bh2[2][4];
#pragma unroll
                    for (int gi = 0; gi < 2; gi++) {
                        const int col = wn * 64 + (gph * 2 + gi) * 16 + (lane & 15);
                        ldm_x4(bh2[gi], Bb + swz128(col, ac));
                    }
#pragma unroll
                    for (int mi = 0; mi < 2; mi++)
#pragma unroll
                        for (int gi = 0; gi < 2; gi++)
#pragma unroll
                            for (int sub = 0; sub < 2; sub++)
                                mma16816(acc[mi][(gph * 2 + gi) * 2 + sub],
                                         ah[mi], bh2[gi][sub], bh2[gi][sub + 2]);
                }
            }
        }
        __syncthreads();
        if (t + 2 < T_STEPS) { loadA(t + 2); CP_COMMIT(); }

        // epilogue: bias + store fp32
        float* xgp = g_xg + (((size_t)(dir * T_STEPS + t) * 40 + mt) * 128) * 1024 + nt * 128;
#pragma unroll
        for (int mi = 0; mi < 2; mi++)
#pragma unroll
            for (int nj = 0; nj < 8; nj++) {
                const int r = wm * 32 + mi * 16 + (lane >> 2);
                const int c = wn * 64 + nj * 8 + (lane & 3) * 2;
                const float b0 = bias_sm[c], b1 = bias_sm[c + 1];
                float2 v0 = { acc[mi][nj][0] + b0, acc[mi][nj][1] + b1 };
                float2 v1 = { acc[mi][nj][2] + b0, acc[mi][nj][3] + b1 };
                *(float2*)&xgp[(size_t)r * 1024 + c] = v0;
                *(float2*)&xgp[(size_t)(r + 8) * 1024 + c] = v1;
            }
    }
}

// ---------------- LSTM step: K=256 in 4 chunks of 64, 2-stage, shfl epilogue ----------
// stage 48KB: A_hi 16K | A_lo 16K | B 16K; 2 stages = 96KB; pack (16.9KB) overlays stage0.
#define ST_SZ    49152
#define SM_TOTAL (2 * ST_SZ)   // 98304

__global__ void __launch_bounds__(256, 2) lstm_step_mma(int s) {
    extern __shared__ __align__(16) unsigned char smem[];
    const uint32_t sbase = smem_u32(smem);
    const int tid = threadIdx.x, wid = tid >> 5, lane = tid & 31;
    const int wm = wid & 3, wn = wid >> 2;
    const int nt = blockIdx.x, mt = blockIdx.y, dir = blockIdx.z;
    const int t = dir ? (T_STEPS - 1 - s) : s;
    const int par = s & 1;

    const __half* Ap = &g_Ah[par][dir][mt][0][0][0];
    const __half* Bp = &g_Bh[dir][nt][0][0];

    auto load_chunk = [&](int ck) {
        const uint32_t stg = sbase + (ck & 1) * ST_SZ;
#pragma unroll
        for (int j = 0; j < 8; j++) {
            int id = tid + j * 256;
            int img = id >> 10, row = (id >> 3) & 127, ch = id & 7;
            cpa16(stg + img * 16384 + swz128(row, ch),
                  &Ap[(size_t)img * 32768 + row * 256 + ck * 64 + ch * 8]);
        }
#pragma unroll
        for (int j = 0; j < 4; j++) {
            int id = tid + j * 256;
            int row = (id >> 3) & 127, ch = id & 7;
            cpa16(stg + 32768 + swz128(row, ch),
                  &Bp[(size_t)row * 256 + ck * 64 + ch * 8]);
        }
    };

    load_chunk(0); CP_COMMIT();
    load_chunk(1); CP_COMMIT();

    // accumulator init from precomputed xg (+bias folded) — overlaps prologue loads
    const float* xgp = g_xg + (((size_t)(dir * T_STEPS + t) * 40 + mt) * 128) * 1024 + nt * 128;
    float acc[2][8][4];
#pragma unroll
    for (int mi = 0; mi < 2; mi++)
#pragma unroll
        for (int nj = 0; nj < 8; nj++) {
            const int r = wm * 32 + mi * 16 + (lane >> 2);
            const int c = wn * 64 + nj * 8 + (lane & 3) * 2;
            float2 v0 = *(const float2*)&xgp[(size_t)r * 1024 + c];
            float2 v1 = *(const float2*)&xgp[(size_t)(r + 8) * 1024 + c];
            acc[mi][nj][0] = v0.x; acc[mi][nj][1] = v0.y;
            acc[mi][nj][2] = v1.x; acc[mi][nj][3] = v1.y;
        }

    // c-state: 16 contiguous floats per thread (fragment layout)
    float* cptr = g_cfrag + (((((size_t)dir * 40 + mt) * 8 + nt) * 8 + wid) * 32 + lane) * 16;
    float creg[16];
    *(float4*)(creg + 0)  = *(const float4*)(cptr + 0);
    *(float4*)(creg + 4)  = *(const float4*)(cptr + 4);
    *(float4*)(creg + 8)  = *(const float4*)(cptr + 8);
    *(float4*)(creg + 12) = *(const float4*)(cptr + 12);

    for (int ck = 0; ck < 4; ck++) {
        if (ck < 3) CP_WAIT1(); else CP_WAIT0();
        __syncthreads();

        const uint32_t stg = sbase + (ck & 1) * ST_SZ;
        const uint32_t Ab0 = stg, Ab1 = stg + 16384;
        const uint32_t Bb = stg + 32768;
#pragma unroll
        for (int ks = 0; ks < 4; ks++) {
            const int ac = 2 * ks + (lane >> 4);
            uint32_t ah[2][4], al[2][4];
#pragma unroll
            for (int fi = 0; fi < 2; fi++) {
                const int row = wm * 32 + fi * 16 + (lane & 15);
                const uint32_t off = swz128(row, ac);
                ldm_x4(ah[fi], Ab0 + off);
                ldm_x4(al[fi], Ab1 + off);
            }
#pragma unroll
            for (int gph = 0; gph < 2; gph++) {
                uint32_t bh2[2][4];
#pragma unroll
                for (int gi = 0; gi < 2; gi++) {
                    const int col = wn * 64 + (gph * 2 + gi) * 16 + (lane & 15);
                    ldm_x4(bh2[gi], Bb + swz128(col, ac));
                }
#pragma unroll
                for (int mi = 0; mi < 2; mi++)
#pragma unroll
                    for (int gi = 0; gi < 2; gi++)
#pragma unroll
                        for (int sub = 0; sub < 2; sub++) {
                            float* d = acc[mi][(gph * 2 + gi) * 2 + sub];
                            mma16816(d, ah[mi], bh2[gi][sub], bh2[gi][sub + 2]);
                            mma16816(d, al[mi], bh2[gi][sub], bh2[gi][sub + 2]);
                        }
            }
        }
        __syncthreads();
        if (ck + 2 < 4) { load_chunk(ck + 2); CP_COMMIT(); }
    }

    // ---------------- epilogue: shfl gate assembly + per-thread cell ----------------
    uint32_t* pack = (uint32_t*)smem;   // [128][33] words = 16896 B (overlays stage 0)
    const int rbase = wm * 32 + (lane >> 2) + ((lane & 1) ? 8 : 0);
    const int hb0 = wn * 16 + ((lane >> 1) & 1);
    const bool evenl = (lane & 1) == 0;
#pragma unroll
    for (int mi = 0; mi < 2; mi++) {
#pragma unroll
        for (int nj = 0; nj < 8; nj++) {
            const float v0 = acc[mi][nj][0], v1 = acc[mi][nj][1];
            const float v2 = acc[mi][nj][2], v3 = acc[mi][nj][3];
            const float p0 = __shfl_xor_sync(0xFFFFFFFFu, v0, 1);
            const float p1 = __shfl_xor_sync(0xFFFFFFFFu, v1, 1);
            const float p2 = __shfl_xor_sync(0xFFFFFFFFu, v2, 1);
            const float p3 = __shfl_xor_sync(0xFFFFFFFFu, v3, 1);
            const float gi_ = evenl ? v0 : p2;
            const float gf_ = evenl ? v1 : p3;
            const float gg_ = evenl ? p0 : v2;
            const float go_ = evenl ? p1 : v3;
            const float iv = fsigm(gi_);
            const float fv = fsigm(gf_);
            const float gv = ftanh(gg_);
            const float ov = fsigm(go_);
            const float cn = fv * creg[mi * 8 + nj] + iv * gv;
            creg[mi * 8 + nj] = cn;
            const float hv = ov * ftanh(cn);
            const int row_l = rbase + mi * 16;
            const int hcol = hb0 + nj * 2;
            if (s == T_STEPS - 1)
                g_h[(size_t)dir * NSEQ * HSZ + (size_t)(mt * 128 + row_l) * HSZ
                    + nt * 32 + hcol] = hv;
            uint16_t hbv, lbv; split_h(hv, hbv, lbv);
            pack[row_l * 33 + hcol] = (uint32_t)hbv | ((uint32_t)lbv << 16);
        }
    }
    *(float4*)(cptr + 0)  = *(float4*)(creg + 0);
    *(float4*)(cptr + 4)  = *(float4*)(creg + 4);
    *(float4*)(cptr + 8)  = *(float4*)(creg + 8);
    *(float4*)(cptr + 12) = *(float4*)(creg + 12);
    __syncthreads();

    // pack phase: coalesced 16B global writes of next-step h (hi + lo images)
    {
        const int n_l = tid >> 1;
        const int halfh = tid & 1;
        const int kcol = nt * 32 + halfh * 16;
        uint32_t wv[16];
#pragma unroll
        for (int i = 0; i < 16; i++) wv[i] = pack[n_l * 33 + halfh * 16 + i];
        uint4 u0, u1;
        uint32_t* w;
        w = (uint32_t*)&u0;
#pragma unroll
        for (int q = 0; q < 4; q++)
            w[q] = (wv[q * 2] & 0xFFFFu) | ((wv[q * 2 + 1] & 0xFFFFu) << 16);
        w = (uint32_t*)&u1;
#pragma unroll
        for (int q = 0; q < 4; q++)
            w[q] = (wv[8 + q * 2] & 0xFFFFu) | ((wv[8 + q * 2 + 1] & 0xFFFFu) << 16);
        *(uint4*)&g_Ah[par ^ 1][dir][mt][0][n_l][kcol]     = u0;
        *(uint4*)&g_Ah[par ^ 1][dir][mt][0][n_l][kcol + 8] = u1;
        w = (uint32_t*)&u0;
#pragma unroll
        for (int q = 0; q < 4; q++)
            w[q] = (wv[q * 2] >> 16) | (wv[q * 2 + 1] & 0xFFFF0000u);
        w = (uint32_t*)&u1;
#pragma unroll
        for (int q = 0; q < 4; q++)
            w[q] = (wv[8 + q * 2] >> 16) | (wv[8 + q * 2 + 1] & 0xFFFF0000u);
        *(uint4*)&g_Ah[par ^ 1][dir][mt][1][n_l][kcol]     = u0;
        *(uint4*)&g_Ah[par ^ 1][dir][mt][1][n_l][kcol + 8] = u1;
    }
}

// ---------------- head ----------------
__global__ __launch_bounds__(256) void head_kernel(
    const float* __restrict__ W1, const float* __restrict__ b1,
    const float* __restrict__ W2, const float* __restrict__ b2,
    float* __restrict__ out)
{
    __shared__ float fea[2560];
    __shared__ float zp[4][64];
    __shared__ float zz[64];
    __shared__ float lg[5];

    const int b = blockIdx.x;
    const int tid = threadIdx.x;
    const float* __restrict__ hF = g_h;
    const float* __restrict__ hB = g_h + NSEQ * HSZ;

    for (int i = tid; i < 2560; i += 256) {
        const int slot = i >> 8;
        const int mcol = i & 255;
        const int n = b * 10 + slot;
        const float v = (mcol < 128) ? hF[(size_t)n * HSZ + mcol] : hB[(size_t)n * HSZ + mcol];
        fea[i] = v;
        out[2560 + (size_t)b * 2560 + i] = v;
    }
    __syncthreads();

    const int j = tid & 63;
    const int p = tid >> 6;
    float sum = 0.0f;
    const int k0 = p * 640;
    for (int k = k0; k < k0 + 640; k++) sum += fea[k] * W1[(size_t)j * 2560 + k];
    zp[p][j] = sum;
    __syncthreads();
    if (tid < 64) zz[tid] = zp[0][tid] + zp[1][tid] + zp[2][tid] + zp[3][tid] + b1[tid];
    __syncthreads();

    if (tid < 5) {
        float ss = b2[tid];
        for (int k = 0; k < 64; k++) ss += zz[k] * W2[tid * 64 + k];
        lg[tid] = ss;
    }
    __syncthreads();
    if (tid == 0) {
        float mx = lg[0];
        for (int k = 1; k < 5; k++) mx = fmaxf(mx, lg[k]);
        float e[5], se = 0.0f;
        for (int k = 0; k < 5; k++) { e[k] = expf(lg[k] - mx); se += e[k]; }
        for (int k = 0; k < 5; k++) out[(size_t)b * 5 + k] = e[k] / se;
    }
}

extern "C" void kernel_launch(void* const* d_in, const int* in_sizes, int n_in,
                              void* d_out, int out_size) {
    const float* x     = (const float*)d_in[0];
    const float* h0    = (const float*)d_in[1];
    const float* c0    = (const float*)d_in[2];
    const float* Wih_f = (const float*)d_in[3];
    const float* Whh_f = (const float*)d_in[4];
    const float* bih_f = (const float*)d_in[5];
    const float* bhh_f = (const float*)d_in[6];
    const float* Wih_b = (const float*)d_in[7];
    const float* Whh_b = (const float*)d_in[8];
    const float* bih_b = (const float*)d_in[9];
    const float* bhh_b = (const float*)d_in[10];
    const float* W1    = (const float*)d_in[11];
    const float* b1    = (const float*)d_in[12];
    const float* W2    = (const float*)d_in[13];
    const float* b2    = (const float*)d_in[14];
    float* out = (float*)d_out;

    cudaFuncSetAttribute(xg_gemm, cudaFuncAttributeMaxDynamicSharedMemorySize, XG_SMEM);
    cudaFuncSetAttribute(lstm_step_mma, cudaFuncAttributeMaxDynamicSharedMemorySize, SM_TOTAL);

    // launches: 0 prepack, 1 xg, 2.. steps -> ncu sample lands on a step
    prepack_all<<<(PRE_TOT + 255) / 256, 256>>>(x, h0, c0, Wih_f, Whh_f, bih_f, bhh_f,
                                                Wih_b, Whh_b, bih_b, bhh_b);
    xg_gemm<<<dim3(8, 40, 2), 256, XG_SMEM>>>();

    dim3 grid(8, 40, 2);
    for (int s = 0; s < T_STEPS; s++) {
        lstm_step_mma<<<grid, 256, SM_TOTAL>>>(s);
    }
    head_kernel<<<NBATCH, 256>>>(W1, b1, W2, b2, out);
}

// round 17
// speedup vs baseline: 1.8648x; 1.2761x over previous
#include <cuda_runtime.h>
#include <cuda_fp16.h>
#include <cstdint>
#include <cstring>
#include <math.h>

// ---------------- problem constants ----------------
#define T_STEPS 30
#define ISZ     100
#define HSZ     256
#define NSEQ    5120
#define NBATCH  512

// ---------------- device scratch (allocation-free rule) ----------------
// Single-pass fp16 everywhere now: one image for x and h.
__device__ __half g_Ax[T_STEPS][40][128][128];      // [t][mt][row][k]  x, k pad 100->128
__device__ __half g_Ah[2][2][40][128][256];         // [par][dir][mt][row][k]  h, hi only
__device__ __half g_Bx[2][8][128][128];             // [dir][nt8][c'][k]  Wih, gate-interleaved
__device__ __half g_Bh[2][8][128][256];             // [dir][nt8][c'][k]  Whh
__device__ float g_bias[2][1024];                   // [dir][c'=h*4+g]
// c-state in MMA-fragment layout: [dir][mt][nt][wid][lane][mi*8+nj] (16 floats per thread)
__device__ float g_cfrag[(size_t)2 * 40 * 8 * 8 * 32 * 16];
__device__ float g_h[2 * NSEQ * HSZ];               // finals only (s==29), standard layout
__device__ float g_xg[(size_t)2 * T_STEPS * 40 * 128 * 1024]; // [dir][t][mt][row][c']

// ---------------- helpers ----------------
__device__ __forceinline__ uint32_t smem_u32(const void* p) {
    uint32_t a;
    asm("{ .reg .u64 t; cvta.to.shared.u64 t, %1; cvt.u32.u64 %0, t; }" : "=r"(a) : "l"(p));
    return a;
}
__device__ __forceinline__ void cpa16(uint32_t dst, const void* src) {
    asm volatile("cp.async.cg.shared.global [%0], [%1], 16;" :: "r"(dst), "l"(src));
}
#define CP_COMMIT() asm volatile("cp.async.commit_group;" ::: "memory")
#define CP_WAIT1()  asm volatile("cp.async.wait_group 1;" ::: "memory")
#define CP_WAIT0()  asm volatile("cp.async.wait_group 0;" ::: "memory")

__device__ __forceinline__ void ldm_x4(uint32_t* r, uint32_t addr) {
    asm volatile("ldmatrix.sync.aligned.m8n8.x4.shared.b16 {%0,%1,%2,%3}, [%4];"
                 : "=r"(r[0]), "=r"(r[1]), "=r"(r[2]), "=r"(r[3]) : "r"(addr));
}
__device__ __forceinline__ void mma16816(float* d, const uint32_t* a, uint32_t b0, uint32_t b1) {
    asm volatile(
        "mma.sync.aligned.m16n8k16.row.col.f32.f16.f16.f32 "
        "{%0,%1,%2,%3}, {%4,%5,%6,%7}, {%8,%9}, {%0,%1,%2,%3};"
        : "+f"(d[0]), "+f"(d[1]), "+f"(d[2]), "+f"(d[3])
        : "r"(a[0]), "r"(a[1]), "r"(a[2]), "r"(a[3]), "r"(b0), "r"(b1));
}
// 128B-row swizzle (8 x 16B chunks per row)
__device__ __forceinline__ uint32_t swz128(int row, int ch) {
    return (uint32_t)(row * 128 + ((ch ^ (row & 7)) << 4));
}
__device__ __forceinline__ float fsigm(float x) {
    float e;
    asm("ex2.approx.f32 %0, %1;" : "=f"(e) : "f"(x * -1.4426950408889634f));
    float r;
    asm("rcp.approx.f32 %0, %1;" : "=f"(r) : "f"(1.0f + e));
    return r;
}
__device__ __forceinline__ float ftanh(float x) { return fmaf(2.0f, fsigm(2.0f * x), -1.0f); }

// ---------------- merged prepack (ONE launch) ----------------
#define SEG_BIAS 2048
#define SEG_W    (2 * 8 * 128 * 384)
#define SEG_X    (T_STEPS * NSEQ * 128)
#define SEG_HC   (2 * NSEQ * HSZ)
#define PRE_TOT  (SEG_BIAS + SEG_W + SEG_X + SEG_HC)

__global__ void prepack_all(const float* __restrict__ x,
                            const float* __restrict__ h0, const float* __restrict__ c0,
                            const float* __restrict__ Wih_f, const float* __restrict__ Whh_f,
                            const float* __restrict__ bih_f, const float* __restrict__ bhh_f,
                            const float* __restrict__ Wih_b, const float* __restrict__ Whh_b,
                            const float* __restrict__ bih_b, const float* __restrict__ bhh_b) {
    int idx = blockIdx.x * blockDim.x + threadIdx.x;
    if (idx < SEG_BIAS) {
        int c = idx & 1023, dir = idx >> 10;
        int h = c >> 2, g = c & 3;
        int row = g * HSZ + h;
        g_bias[dir][c] = dir ? (bih_b[row] + bhh_b[row]) : (bih_f[row] + bhh_f[row]);
        return;
    }
    idx -= SEG_BIAS;
    if (idx < SEG_W) {
        int k = idx % 384;
        int rest = idx / 384;
        int c = rest & 127;
        rest >>= 7;
        int nt = rest & 7;
        int dir = rest >> 3;
        const float* Wih = dir ? Wih_b : Wih_f;
        const float* Whh = dir ? Whh_b : Whh_f;
        int hg = nt * 32 + (c >> 2);
        int g = c & 3;
        int row = g * HSZ + hg;
        if (k < 128) {
            float v = (k < ISZ) ? Wih[(size_t)row * ISZ + k] : 0.0f;
            g_Bx[dir][nt][c][k] = __float2half_rn(v);
        } else {
            float v = Whh[(size_t)row * HSZ + (k - 128)];
            g_Bh[dir][nt][c][k - 128] = __float2half_rn(v);
        }
        return;
    }
    idx -= SEG_W;
    if (idx < SEG_X) {
        int k = idx & 127;
        int n = (idx >> 7) % NSEQ;
        int t = idx / (NSEQ * 128);
        float v = (k < ISZ) ? x[((size_t)n * T_STEPS + t) * ISZ + k] : 0.0f;
        int mt = n >> 7, m = n & 127;
        g_Ax[t][mt][m][k] = __float2half_rn(v);
        return;
    }
    idx -= SEG_X;
    if (idx < SEG_HC) {
        int k = idx & 255;
        int n = (idx >> 8) % NSEQ;
        int d = idx / (NSEQ * HSZ);
        // c0 -> fragment layout
        {
            int mt = n >> 7, row_l = n & 127;
            int nt = k >> 5, h_l = k & 31;
            int wm = row_l >> 5, mi = (row_l >> 4) & 1, rsub = row_l & 15;
            int wn = h_l >> 4, nj = (h_l & 15) >> 1, hbit = h_l & 1;
            int lane = ((rsub & 7) << 2) | (hbit << 1) | (rsub >> 3);
            int wid = wm | (wn << 2);
            size_t fidx = (((((size_t)d * 40 + mt) * 8 + nt) * 8 + wid) * 32 + lane) * 16
                          + mi * 8 + nj;
            g_cfrag[fidx] = c0[idx];
        }
        // h0 -> packed image (parity 0), hi only
        int mt = n >> 7, m = n & 127;
        g_Ah[0][d][mt][m][k] = __float2half_rn(h0[idx]);
    }
}

// ---------------- xg GEMM: 1-pass fp16, N=128 tiles, one t per iteration (30 iters) ----
// smem: B 32KB (2 blocks kh*16384 of [c128][k64]) @0 | A stages 2x32KB @32768 | bias @98304
#define XG_SMEM  (32768 + 2 * 32768 + 512)   // 98816

__global__ void __launch_bounds__(256, 2) xg_gemm(void) {
    extern __shared__ __align__(16) unsigned char smem[];
    const uint32_t sbase = smem_u32(smem);
    const int tid = threadIdx.x, wid = tid >> 5, lane = tid & 31;
    const int wm = wid & 3, wn = wid >> 2;   // warp tile: 32 rows x 64 cols
    const int nt = blockIdx.x;               // 8 tiles of 128 cols
    const int mt = blockIdx.y, dir = blockIdx.z;

    float* bias_sm = (float*)(smem + 98304);
    if (tid < 128) bias_sm[tid] = g_bias[dir][nt * 128 + tid];

    // load resident B (32KB): 2 blocks (kh) of [c 128][k 64]
    {
#pragma unroll
        for (int j = 0; j < 8; j++) {
            int id = tid + j * 256;
            int kh = id >> 10, row = (id >> 3) & 127, ch = id & 7;
            cpa16(sbase + kh * 16384 + swz128(row, ch),
                  &g_Bx[dir][nt][row][kh * 64 + ch * 8]);
        }
    }
    CP_COMMIT();

    auto loadA = [&](int t) {
        const uint32_t stg = sbase + 32768 + (t & 1) * 32768;
#pragma unroll
        for (int j = 0; j < 8; j++) {
            int id = tid + j * 256;
            int kh = id >> 10, row = (id >> 3) & 127, ch = id & 7;
            cpa16(stg + kh * 16384 + swz128(row, ch),
                  &g_Ax[t][mt][row][kh * 64 + ch * 8]);
        }
    };
    loadA(0); CP_COMMIT();
    loadA(1); CP_COMMIT();

    for (int t = 0; t < T_STEPS; t++) {
        if (t < T_STEPS - 1) CP_WAIT1(); else CP_WAIT0();
        __syncthreads();

        float acc[2][8][4];
#pragma unroll
        for (int mi = 0; mi < 2; mi++)
#pragma unroll
            for (int nj = 0; nj < 8; nj++)
#pragma unroll
                for (int e = 0; e < 4; e++) acc[mi][nj][e] = 0.0f;

        const uint32_t astg = sbase + 32768 + (t & 1) * 32768;
#pragma unroll
        for (int kh = 0; kh < 2; kh++) {
            const uint32_t Ab = astg + kh * 16384;
            const uint32_t Bb = sbase + kh * 16384;
#pragma unroll
            for (int ks = 0; ks < 4; ks++) {
                const int ac = 2 * ks + (lane >> 4);
                uint32_t ah[2][4];
#pragma unroll
                for (int fi = 0; fi < 2; fi++) {
                    const int row = wm * 32 + fi * 16 + (lane & 15);
                    ldm_x4(ah[fi], Ab + swz128(row, ac));
                }
#pragma unroll
                for (int gph = 0; gph < 2; gph++) {
                    uint32_t bh2[2][4];
#pragma unroll
                    for (int gi = 0; gi < 2; gi++) {
                        const int col = wn * 64 + (gph * 2 + gi) * 16 + (lane & 15);
                        ldm_x4(bh2[gi], Bb + swz128(col, ac));
                    }
#pragma unroll
                    for (int mi = 0; mi < 2; mi++)
#pragma unroll
                        for (int gi = 0; gi < 2; gi++)
#pragma unroll
                            for (int sub = 0; sub < 2; sub++)
                                mma16816(acc[mi][(gph * 2 + gi) * 2 + sub],
                                         ah[mi], bh2[gi][sub], bh2[gi][sub + 2]);
                }
            }
        }
        __syncthreads();
        if (t + 2 < T_STEPS) { loadA(t + 2); CP_COMMIT(); }

        // epilogue: bias + store fp32
        float* xgp = g_xg + (((size_t)(dir * T_STEPS + t) * 40 + mt) * 128) * 1024 + nt * 128;
#pragma unroll
        for (int mi = 0; mi < 2; mi++)
#pragma unroll
            for (int nj = 0; nj < 8; nj++) {
                const int r = wm * 32 + mi * 16 + (lane >> 2);
                const int c = wn * 64 + nj * 8 + (lane & 3) * 2;
                const float b0 = bias_sm[c], b1 = bias_sm[c + 1];
                float2 v0 = { acc[mi][nj][0] + b0, acc[mi][nj][1] + b1 };
                float2 v1 = { acc[mi][nj][2] + b0, acc[mi][nj][3] + b1 };
                *(float2*)&xgp[(size_t)r * 1024 + c] = v0;
                *(float2*)&xgp[(size_t)(r + 8) * 1024 + c] = v1;
            }
    }
}

// ---------------- LSTM step: 1-pass fp16, K=256 in 4 chunks of 64, 2-stage ----------
// stage 32KB: A 16K | B 16K; 2 stages = 64KB; pack (16.9KB) overlays stage0.
#define ST_SZ    32768
#define SM_TOTAL (2 * ST_SZ)   // 65536

__global__ void __launch_bounds__(256, 2) lstm_step_mma(int s) {
    extern __shared__ __align__(16) unsigned char smem[];
    const uint32_t sbase = smem_u32(smem);
    const int tid = threadIdx.x, wid = tid >> 5, lane = tid & 31;
    const int wm = wid & 3, wn = wid >> 2;
    const int nt = blockIdx.x, mt = blockIdx.y, dir = blockIdx.z;
    const int t = dir ? (T_STEPS - 1 - s) : s;
    const int par = s & 1;

    const __half* Ap = &g_Ah[par][dir][mt][0][0];
    const __half* Bp = &g_Bh[dir][nt][0][0];

    auto load_chunk = [&](int ck) {
        const uint32_t stg = sbase + (ck & 1) * ST_SZ;
#pragma unroll
        for (int j = 0; j < 4; j++) {
            int id = tid + j * 256;
            int row = (id >> 3) & 127, ch = id & 7;
            cpa16(stg + swz128(row, ch),
                  &Ap[(size_t)row * 256 + ck * 64 + ch * 8]);
        }
#pragma unroll
        for (int j = 0; j < 4; j++) {
            int id = tid + j * 256;
            int row = (id >> 3) & 127, ch = id & 7;
            cpa16(stg + 16384 + swz128(row, ch),
                  &Bp[(size_t)row * 256 + ck * 64 + ch * 8]);
        }
    };

    load_chunk(0); CP_COMMIT();
    load_chunk(1); CP_COMMIT();

    // accumulator init from precomputed xg (+bias folded) — overlaps prologue loads
    const float* xgp = g_xg + (((size_t)(dir * T_STEPS + t) * 40 + mt) * 128) * 1024 + nt * 128;
    float acc[2][8][4];
#pragma unroll
    for (int mi = 0; mi < 2; mi++)
#pragma unroll
        for (int nj = 0; nj < 8; nj++) {
            const int r = wm * 32 + mi * 16 + (lane >> 2);
            const int c = wn * 64 + nj * 8 + (lane & 3) * 2;
            float2 v0 = *(const float2*)&xgp[(size_t)r * 1024 + c];
            float2 v1 = *(const float2*)&xgp[(size_t)(r + 8) * 1024 + c];
            acc[mi][nj][0] = v0.x; acc[mi][nj][1] = v0.y;
            acc[mi][nj][2] = v1.x; acc[mi][nj][3] = v1.y;
        }

    // c-state: 16 contiguous floats per thread (fragment layout)
    float* cptr = g_cfrag + (((((size_t)dir * 40 + mt) * 8 + nt) * 8 + wid) * 32 + lane) * 16;
    float creg[16];
    *(float4*)(creg + 0)  = *(const float4*)(cptr + 0);
    *(float4*)(creg + 4)  = *(const float4*)(cptr + 4);
    *(float4*)(creg + 8)  = *(const float4*)(cptr + 8);
    *(float4*)(creg + 12) = *(const float4*)(cptr + 12);

    for (int ck = 0; ck < 4; ck++) {
        if (ck < 3) CP_WAIT1(); else CP_WAIT0();
        __syncthreads();

        const uint32_t stg = sbase + (ck & 1) * ST_SZ;
        const uint32_t Ab = stg;
        const uint32_t Bb = stg + 16384;
#pragma unroll
        for (int ks = 0; ks < 4; ks++) {
            const int ac = 2 * ks + (lane >> 4);
            uint32_t ah[2][4];
#pragma unroll
            for (int fi = 0; fi < 2; fi++) {
                const int row = wm * 32 + fi * 16 + (lane & 15);
                ldm_x4(ah[fi], Ab + swz128(row, ac));
            }
#pragma unroll
            for (int gph = 0; gph < 2; gph++) {
                uint32_t bh2[2][4];
#pragma unroll
                for (int gi = 0; gi < 2; gi++) {
                    const int col = wn * 64 + (gph * 2 + gi) * 16 + (lane & 15);
                    ldm_x4(bh2[gi], Bb + swz128(col, ac));
                }
#pragma unroll
                for (int mi = 0; mi < 2; mi++)
#pragma unroll
                    for (int gi = 0; gi < 2; gi++)
#pragma unroll
                        for (int sub = 0; sub < 2; sub++)
                            mma16816(acc[mi][(gph * 2 + gi) * 2 + sub],
                                     ah[mi], bh2[gi][sub], bh2[gi][sub + 2]);
            }
        }
        __syncthreads();
        if (ck + 2 < 4) { load_chunk(ck + 2); CP_COMMIT(); }
    }

    // ---------------- epilogue: shfl gate assembly + per-thread cell ----------------
    uint32_t* pack = (uint32_t*)smem;   // [128][33] words = 16896 B (overlays stage 0)
    const int rbase = wm * 32 + (lane >> 2) + ((lane & 1) ? 8 : 0);
    const int hb0 = wn * 16 + ((lane >> 1) & 1);
    const bool evenl = (lane & 1) == 0;
#pragma unroll
    for (int mi = 0; mi < 2; mi++) {
#pragma unroll
        for (int nj = 0; nj < 8; nj++) {
            const float v0 = acc[mi][nj][0], v1 = acc[mi][nj][1];
            const float v2 = acc[mi][nj][2], v3 = acc[mi][nj][3];
            const float p0 = __shfl_xor_sync(0xFFFFFFFFu, v0, 1);
            const float p1 = __shfl_xor_sync(0xFFFFFFFFu, v1, 1);
            const float p2 = __shfl_xor_sync(0xFFFFFFFFu, v2, 1);
            const float p3 = __shfl_xor_sync(0xFFFFFFFFu, v3, 1);
            const float gi_ = evenl ? v0 : p2;
            const float gf_ = evenl ? v1 : p3;
            const float gg_ = evenl ? p0 : v2;
            const float go_ = evenl ? p1 : v3;
            const float iv = fsigm(gi_);
            const float fv = fsigm(gf_);
            const float gv = ftanh(gg_);
            const float ov = fsigm(go_);
            const float cn = fv * creg[mi * 8 + nj] + iv * gv;
            creg[mi * 8 + nj] = cn;
            const float hv = ov * ftanh(cn);
            const int row_l = rbase + mi * 16;
            const int hcol = hb0 + nj * 2;
            if (s == T_STEPS - 1)
                g_h[(size_t)dir * NSEQ * HSZ + (size_t)(mt * 128 + row_l) * HSZ
                    + nt * 32 + hcol] = hv;
            __half hh = __float2half_rn(hv);
            uint16_t hbv; memcpy(&hbv, &hh, 2);
            pack[row_l * 33 + hcol] = (uint32_t)hbv;
        }
    }
    *(float4*)(cptr + 0)  = *(float4*)(creg + 0);
    *(float4*)(cptr + 4)  = *(float4*)(creg + 4);
    *(float4*)(cptr + 8)  = *(float4*)(creg + 8);
    *(float4*)(cptr + 12) = *(float4*)(creg + 12);
    __syncthreads();

    // pack phase: coalesced 16B global writes of next-step h (hi image only)
    {
        const int n_l = tid >> 1;
        const int halfh = tid & 1;
        const int kcol = nt * 32 + halfh * 16;
        uint32_t wv[16];
#pragma unroll
        for (int i = 0; i < 16; i++) wv[i] = pack[n_l * 33 + halfh * 16 + i];
        uint4 u0, u1;
        uint32_t* w;
        w = (uint32_t*)&u0;
#pragma unroll
        for (int q = 0; q < 4; q++)
            w[q] = (wv[q * 2] & 0xFFFFu) | ((wv[q * 2 + 1] & 0xFFFFu) << 16);
        w = (uint32_t*)&u1;
#pragma unroll
        for (int q = 0; q < 4; q++)
            w[q] = (wv[8 + q * 2] & 0xFFFFu) | ((wv[8 + q * 2 + 1] & 0xFFFFu) << 16);
        *(uint4*)&g_Ah[par ^ 1][dir][mt][n_l][kcol]     = u0;
        *(uint4*)&g_Ah[par ^ 1][dir][mt][n_l][kcol + 8] = u1;
    }
}

// ---------------- head ----------------
__global__ __launch_bounds__(256) void head_kernel(
    const float* __restrict__ W1, const float* __restrict__ b1,
    const float* __restrict__ W2, const float* __restrict__ b2,
    float* __restrict__ out)
{
    __shared__ float fea[2560];
    __shared__ float zp[4][64];
    __shared__ float zz[64];
    __shared__ float lg[5];

    const int b = blockIdx.x;
    const int tid = threadIdx.x;
    const float* __restrict__ hF = g_h;
    const float* __restrict__ hB = g_h + NSEQ * HSZ;

    for (int i = tid; i < 2560; i += 256) {
        const int slot = i >> 8;
        const int mcol = i & 255;
        const int n = b * 10 + slot;
        const float v = (mcol < 128) ? hF[(size_t)n * HSZ + mcol] : hB[(size_t)n * HSZ + mcol];
        fea[i] = v;
        out[2560 + (size_t)b * 2560 + i] = v;
    }
    __syncthreads();

    const int j = tid & 63;
    const int p = tid >> 6;
    float sum = 0.0f;
    const int k0 = p * 640;
    for (int k = k0; k < k0 + 640; k++) sum += fea[k] * W1[(size_t)j * 2560 + k];
    zp[p][j] = sum;
    __syncthreads();
    if (tid < 64) zz[tid] = zp[0][tid] + zp[1][tid] + zp[2][tid] + zp[3][tid] + b1[tid];
    __syncthreads();

    if (tid < 5) {
        float ss = b2[tid];
        for (int k = 0; k < 64; k++) ss += zz[k] * W2[tid * 64 + k];
        lg[tid] = ss;
    }
    __syncthreads();
    if (tid == 0) {
        float mx = lg[0];
        for (int k = 1; k < 5; k++) mx = fmaxf(mx, lg[k]);
        float e[5], se = 0.0f;
        for (int k = 0; k < 5; k++) { e[k] = expf(lg[k] - mx); se += e[k]; }
        for (int k = 0; k < 5; k++) out[(size_t)b * 5 + k] = e[k] / se;
    }
}

extern "C" void kernel_launch(void* const* d_in, const int* in_sizes, int n_in,
                              void* d_out, int out_size) {
    const float* x     = (const float*)d_in[0];
    const float* h0    = (const float*)d_in[1];
    const float* c0    = (const float*)d_in[2];
    const float* Wih_f = (const float*)d_in[3];
    const float* Whh_f = (const float*)d_in[4];
    const float* bih_f = (const float*)d_in[5];
    const float* bhh_f = (const float*)d_in[6];
    const float* Wih_b = (const float*)d_in[7];
    const float* Whh_b = (const float*)d_in[8];
    const float* bih_b = (const float*)d_in[9];
    const float* bhh_b = (const float*)d_in[10];
    const float* W1    = (const float*)d_in[11];
    const float* b1    = (const float*)d_in[12];
    const float* W2    = (const float*)d_in[13];
    const float* b2    = (const float*)d_in[14];
    float* out = (float*)d_out;

    cudaFuncSetAttribute(xg_gemm, cudaFuncAttributeMaxDynamicSharedMemorySize, XG_SMEM);
    cudaFuncSetAttribute(lstm_step_mma, cudaFuncAttributeMaxDynamicSharedMemorySize, SM_TOTAL);

    // launches: 0 prepack, 1 xg, 2.. steps -> ncu sample lands on a step
    prepack_all<<<(PRE_TOT + 255) / 256, 256>>>(x, h0, c0, Wih_f, Whh_f, bih_f, bhh_f,
                                                Wih_b, Whh_b, bih_b, bhh_b);
    xg_gemm<<<dim3(8, 40, 2), 256, XG_SMEM>>>();

    dim3 grid(8, 40, 2);
    for (int s = 0; s < T_STEPS; s++) {
        lstm_step_mma<<<grid, 256, SM_TOTAL>>>(s);
    }
    head_kernel<<<NBATCH, 256>>>(W1, b1, W2, b2, out);
}